// round 13
// baseline (speedup 1.0000x reference)
#include <cuda_runtime.h>
#include <cuda_bf16.h>
#include <math.h>
#include <stdint.h>

#define S_LEN 2048
#define HID   4096
#define NH    32
#define NKV   8
#define HD    128
#define KVDIM 1024
#define KDIM  4096
#define KS    (KDIM / 16)   // 256 k16 units
#define NS32  (KDIM / 32)   // 128 k32 stages

// ---------------- scratch ----------------
__device__ __align__(16) __nv_bfloat16 g_qh[S_LEN * HID],  g_ql[S_LEN * HID];
__device__ __align__(16) __nv_bfloat16 g_kh[S_LEN * KVDIM], g_kl[S_LEN * KVDIM];
__device__ __align__(16) __nv_bfloat16 g_vh[S_LEN * KVDIM], g_vl[S_LEN * KVDIM];
__device__ float4 g_pa_hs[(S_LEN / 128) * KS * 512];
__device__ float4 g_pa_at[(S_LEN / 128) * KS * 512];
__device__ float4 g_pb_wq[(HID / 128) * KS * 512];
__device__ float4 g_pb_wk[(KVDIM / 128) * KS * 512];
__device__ float4 g_pb_wv[(KVDIM / 128) * KS * 512];
__device__ float4 g_pb_wo[(HID / 128) * KS * 512];

// ---------------- helpers ----------------
__device__ __forceinline__ uint32_t smem_u32(const void* p) {
    uint32_t a;
    asm("{ .reg .u64 t; cvta.to.shared.u64 t, %1; cvt.u32.u64 %0, t; }" : "=r"(a) : "l"(p));
    return a;
}
__device__ __forceinline__ void cp_async16s(uint32_t s, const void* g) {
    asm volatile("cp.async.cg.shared.global [%0], [%1], 16;\n" :: "r"(s), "l"(g));
}
__device__ __forceinline__ float f2tf_f(float x) {
    uint32_t u;
    asm("cvt.rna.tf32.f32 %0, %1;" : "=r"(u) : "f"(x));
    return __uint_as_float(u);
}
__device__ __forceinline__ void mma_tf32(float c[4], const uint32_t a[4],
                                         uint32_t b0, uint32_t b1) {
    asm volatile(
        "mma.sync.aligned.m16n8k8.row.col.f32.tf32.tf32.f32 "
        "{%0,%1,%2,%3},{%4,%5,%6,%7},{%8,%9},{%0,%1,%2,%3};"
        : "+f"(c[0]), "+f"(c[1]), "+f"(c[2]), "+f"(c[3])
        : "r"(a[0]), "r"(a[1]), "r"(a[2]), "r"(a[3]), "r"(b0), "r"(b1));
}

// ---------------------------------------------------------------------------
// Unified pack: tf32-round + fragment-pack for all 5 tensors, smem-staged.
// ---------------------------------------------------------------------------
#define SEG_HS 16
#define SEG_WQ 48
#define SEG_WK 56
#define SEG_WV 64
#define SEG_WO 96
#define PACK_BLOCKS (SEG_WO * 256)

__global__ __launch_bounds__(256) void pack_all(
    const float* __restrict__ hs, const float* __restrict__ Wq,
    const float* __restrict__ Wk, const float* __restrict__ Wv,
    const float* __restrict__ Wo,
    float4* __restrict__ Phs, float4* __restrict__ Pwq,
    float4* __restrict__ Pwk, float4* __restrict__ Pwv,
    float4* __restrict__ Pwo) {
    __shared__ float S[128 * 36];
    const int tid  = threadIdx.x;
    const int tile = blockIdx.x;
    const int ks   = tile & 255;
    const int seg  = tile >> 8;

    const float* X;  float4* P;  int rb, amode;
    if (seg < SEG_HS)      { X = hs; P = Phs; rb = seg;          amode = 1; }
    else if (seg < SEG_WQ) { X = Wq; P = Pwq; rb = seg - SEG_HS; amode = 0; }
    else if (seg < SEG_WK) { X = Wk; P = Pwk; rb = seg - SEG_WQ; amode = 0; }
    else if (seg < SEG_WV) { X = Wv; P = Pwv; rb = seg - SEG_WK; amode = 0; }
    else                   { X = Wo; P = Pwo; rb = seg - SEG_WV; amode = 0; }

    const float* Xb = X + (size_t)rb * 128 * KDIM + ks * 16;
    #pragma unroll
    for (int j = 0; j < 2; ++j) {
        int li = tid + j * 256;
        int row = li >> 2, c4 = (li & 3) << 2;
        float4 v = *(const float4*)(Xb + (size_t)row * KDIM + c4);
        *(float4*)&S[row * 36 + c4] = v;
    }
    __syncthreads();

    float4* Pb = P + (((size_t)rb << 17) | ((size_t)ks << 9));
    #pragma unroll
    for (int j = 0; j < 2; ++j) {
        int oo = tid + j * 256;
        int lane = oo & 31, mb = (oo >> 5) & 7, kk = oo >> 8;
        int g = lane >> 2, t = lane & 3;
        int r = mb * 16 + g, c = kk * 8 + t;
        float a0 = S[r * 36 + c];
        float a1 = S[(r + 8) * 36 + c];
        float a2 = S[r * 36 + c + 4];
        float a3 = S[(r + 8) * 36 + c + 4];
        float4 pv;
        if (amode) pv = make_float4(f2tf_f(a0), f2tf_f(a1), f2tf_f(a2), f2tf_f(a3));
        else       pv = make_float4(f2tf_f(a0), f2tf_f(a2), f2tf_f(a1), f2tf_f(a3));
        Pb[oo] = pv;
    }
}

// ---------------------------------------------------------------------------
// Fragment-packed TF32 GEMM v4: CTA 128x256, warp 64x64, k=32/stage,
// 4-stage ring (192 KB), cp.async INTERLEAVED with MMA (3/thread/kk2 step),
// single __syncthreads per stage. Accumulation order bit-identical to v2/v3.
// ---------------------------------------------------------------------------
#define STG_F4  3072                 // A 1024 + B0 1024 + B1 1024 float4
#define STG_BY  (STG_F4 * 16)        // 49152 bytes
#define PK2_SMEM (4 * STG_BY)        // 196608 bytes

__global__ __launch_bounds__(256, 1)
void gemm_pk2(const float4* __restrict__ PA,
              const float4* __restrict__ B0, int nt0, float* C0f,
              __nv_bfloat16* C0h, __nv_bfloat16* C0l, int ld0,
              const float4* __restrict__ B1, int nt1, float* C1f,
              __nv_bfloat16* C1h, __nv_bfloat16* C1l, int ld1,
              const float4* __restrict__ B2, int nt2, float* C2f,
              __nv_bfloat16* C2h, __nv_bfloat16* C2l, int ld2,
              int split) {
    extern __shared__ float4 sm4[];
    const int tid = threadIdx.x, warp = tid >> 5, lane = tid & 31;
    const int g = lane >> 2, t = lane & 3;
    const int wm = warp & 1;
    const int wn = warp >> 1;
    const uint32_t sb = smem_u32(sm4);

    int nt = blockIdx.x;
    const float4* PB;  float* Cf;  __nv_bfloat16 *Ch, *Cl;  int ld;
    if (nt < nt0)            { PB = B0; Cf = C0f; Ch = C0h; Cl = C0l; ld = ld0; }
    else if (nt < nt0 + nt1) { nt -= nt0;       PB = B1; Cf = C1f; Ch = C1h; Cl = C1l; ld = ld1; }
    else                     { nt -= nt0 + nt1; PB = B2; Cf = C2f; Ch = C2h; Cl = C2l; ld = ld2; }

    const size_t abase  = (size_t)blockIdx.y * KS * 512;
    const size_t bbase0 = (size_t)(2 * nt)     * KS * 512;
    const size_t bbase1 = (size_t)(2 * nt + 1) * KS * 512;

    float c[4][8][4];
    #pragma unroll
    for (int mt = 0; mt < 4; mt++)
        #pragma unroll
        for (int ntb = 0; ntb < 8; ntb++)
            #pragma unroll
            for (int i = 0; i < 4; i++) c[mt][ntb][i] = 0.f;

    // source pointer for packed element cix (0..3071) of k32 stage s
    #define PK_SRC(s_, cix_)                                                    \
        (((cix_) < 1024) ? (PA + abase  + (size_t)(s_) * 1024 + (cix_))         \
         : ((cix_) < 2048) ? (PB + bbase0 + (size_t)(s_) * 1024 + ((cix_) - 1024)) \
                           : (PB + bbase1 + (size_t)(s_) * 1024 + ((cix_) - 2048)))

    // burst-stage (prologue only)
    #define STAGE_BURST(s_)                                                     \
        do {                                                                    \
            const uint32_t db = sb + (uint32_t)((s_) & 3) * STG_BY;             \
            _Pragma("unroll")                                                   \
            for (int i_ = 0; i_ < 12; ++i_) {                                   \
                int cix = tid + i_ * 256;                                       \
                cp_async16s(db + (uint32_t)cix * 16u, PK_SRC(s_, cix));         \
            }                                                                   \
            asm volatile("cp.async.commit_group;\n" ::);                        \
        } while (0)

    STAGE_BURST(0);
    STAGE_BURST(1);
    STAGE_BURST(2);

    const int bblk = wn >> 1;
    const int bnp0 = (wn & 1) * 4;

    for (int s = 0; s < NS32; ++s) {
        if (s <= NS32 - 3)      asm volatile("cp.async.wait_group 2;\n" ::);
        else if (s == NS32 - 2) asm volatile("cp.async.wait_group 1;\n" ::);
        else                    asm volatile("cp.async.wait_group 0;\n" ::);
        __syncthreads();

        const bool     do_pf = (s + 3 < NS32);
        const int      pfs   = s + 3;
        const uint32_t pfdb  = sb + (uint32_t)((s + 3) & 3) * STG_BY;

        const float4* As4 = sm4 + (s & 3) * STG_F4;
        const float4* Bs4 = As4 + 1024 + bblk * 1024;
        #pragma unroll
        for (int kk2 = 0; kk2 < 4; ++kk2) {     // 4 x k8 within k32 stage
            // interleaved prefetch: 3 cp.async per thread per step
            if (do_pf) {
                #pragma unroll
                for (int j = 0; j < 3; ++j) {
                    int cix = tid + (kk2 * 3 + j) * 256;
                    cp_async16s(pfdb + (uint32_t)cix * 16u, PK_SRC(pfs, cix));
                }
            }
            const int koffs = (kk2 >> 1) * 512 + (kk2 & 1) * 256;
            float4 av[4], bv[4];
            #pragma unroll
            for (int mt = 0; mt < 4; ++mt)
                av[mt] = As4[koffs + (wm * 4 + mt) * 32 + lane];
            #pragma unroll
            for (int np = 0; np < 4; ++np)
                bv[np] = Bs4[koffs + (bnp0 + np) * 32 + lane];
            #pragma unroll
            for (int mt = 0; mt < 4; ++mt) {
                uint32_t a[4] = { __float_as_uint(av[mt].x), __float_as_uint(av[mt].y),
                                  __float_as_uint(av[mt].z), __float_as_uint(av[mt].w) };
                #pragma unroll
                for (int ntb = 0; ntb < 8; ++ntb) {
                    const float4& b = bv[ntb >> 1];
                    uint32_t b0 = (ntb & 1) ? __float_as_uint(b.z) : __float_as_uint(b.x);
                    uint32_t b1 = (ntb & 1) ? __float_as_uint(b.w) : __float_as_uint(b.y);
                    mma_tf32(c[mt][ntb], a, b0, b1);
                }
            }
        }
        if (do_pf) asm volatile("cp.async.commit_group;\n" ::);
    }

    const int bm = blockIdx.y * 128, bn = nt * 256;
    #pragma unroll
    for (int mt = 0; mt < 4; ++mt) {
        #pragma unroll
        for (int ntb = 0; ntb < 8; ++ntb) {
            const int row = bm + wm * 64 + mt * 16 + g;
            const int col = bn + wn * 64 + ntb * 8 + 2 * t;
            if (!split) {
                *(float2*)&Cf[(size_t)row * ld + col]       = make_float2(c[mt][ntb][0], c[mt][ntb][1]);
                *(float2*)&Cf[(size_t)(row + 8) * ld + col] = make_float2(c[mt][ntb][2], c[mt][ntb][3]);
            } else {
                size_t e0 = (size_t)row * ld + col;
                size_t e1 = (size_t)(row + 8) * ld + col;
                __nv_bfloat162 h0 = __floats2bfloat162_rn(c[mt][ntb][0], c[mt][ntb][1]);
                __nv_bfloat162 h1 = __floats2bfloat162_rn(c[mt][ntb][2], c[mt][ntb][3]);
                __nv_bfloat162 l0 = __floats2bfloat162_rn(c[mt][ntb][0] - __low2float(h0),
                                                          c[mt][ntb][1] - __high2float(h0));
                __nv_bfloat162 l1 = __floats2bfloat162_rn(c[mt][ntb][2] - __low2float(h1),
                                                          c[mt][ntb][3] - __high2float(h1));
                *(__nv_bfloat162*)&Ch[e0] = h0;  *(__nv_bfloat162*)&Cl[e0] = l0;
                *(__nv_bfloat162*)&Ch[e1] = h1;  *(__nv_bfloat162*)&Cl[e1] = l1;
            }
        }
    }
}

// ---------------------------------------------------------------------------
// Attention: ABQ=64, ABK=32, 4 warps, 2 CTAs/SM, Q fragments hoisted,
// double-buffered KV ring, packed-A fragment epilogue. (round-12 kernel)
// ---------------------------------------------------------------------------
#define ABQ  64
#define ABK  32
#define APAD 136
#define KVBUF (4 * ABK * APAD)
#define ASMEM2 ((2 * ABQ * APAD + 2 * KVBUF) * 2)

__device__ __forceinline__ void ldsm_x4(uint32_t r[4], const void* p) {
    uint32_t a = smem_u32(p);
    asm volatile("ldmatrix.sync.aligned.m8n8.x4.shared.b16 {%0,%1,%2,%3}, [%4];"
                 : "=r"(r[0]), "=r"(r[1]), "=r"(r[2]), "=r"(r[3]) : "r"(a));
}
__device__ __forceinline__ void ldsm_x4_t(uint32_t r[4], const void* p) {
    uint32_t a = smem_u32(p);
    asm volatile("ldmatrix.sync.aligned.m8n8.x4.trans.shared.b16 {%0,%1,%2,%3}, [%4];"
                 : "=r"(r[0]), "=r"(r[1]), "=r"(r[2]), "=r"(r[3]) : "r"(a));
}
__device__ __forceinline__ void mma_bf16(float c[4], const uint32_t a[4],
                                         uint32_t b0, uint32_t b1) {
    asm volatile(
        "mma.sync.aligned.m16n8k16.row.col.f32.bf16.bf16.f32 "
        "{%0,%1,%2,%3},{%4,%5,%6,%7},{%8,%9},{%0,%1,%2,%3};"
        : "+f"(c[0]), "+f"(c[1]), "+f"(c[2]), "+f"(c[3])
        : "r"(a[0]), "r"(a[1]), "r"(a[2]), "r"(a[3]), "r"(b0), "r"(b1));
}

__device__ __forceinline__ int nextv(int kb, int kb_max, int q0, int n_init, int n_local) {
    while (kb <= kb_max) {
        int k0 = kb * ABK;
        if (!(k0 >= n_init && (q0 - (k0 + ABK - 1)) >= n_local)) break;
        kb++;
    }
    return kb;
}

__global__ __launch_bounds__(128, 2) void attn_cp(
    const __nv_bfloat16* __restrict__ Qhg, const __nv_bfloat16* __restrict__ Qlg,
    const __nv_bfloat16* __restrict__ Khg, const __nv_bfloat16* __restrict__ Klg,
    const __nv_bfloat16* __restrict__ Vhg, const __nv_bfloat16* __restrict__ Vlg,
    float4* __restrict__ PAout,
    const int* __restrict__ n_init_p, const int* __restrict__ n_local_p) {

    extern __shared__ __nv_bfloat16 smb[];
    __nv_bfloat16* Qh  = smb;
    __nv_bfloat16* Ql  = Qh + ABQ * APAD;
    __nv_bfloat16* KV0 = Ql + ABQ * APAD;

    const int h   = blockIdx.y;
    const int q0  = blockIdx.x * ABQ;
    const int hkv = h >> 2;
    const int n_init  = *n_init_p;
    const int n_local = *n_local_p;

    const int tid  = threadIdx.x;
    const int warp = tid >> 5;
    const int lane = tid & 31;
    const int g    = lane >> 2;
    const int t    = lane & 3;
    const int grp  = lane >> 3;

    const int kb_max = (q0 + ABQ - 1) / ABK;

    #define STAGE_KV(bufp, k0_)                                                  \
        do {                                                                     \
            const __nv_bfloat16* gsrc_[4] = { Khg, Klg, Vhg, Vlg };              \
            _Pragma("unroll")                                                    \
            for (int it_ = 0; it_ < 16; ++it_) {                                 \
                int idx = tid + it_ * 128;                                       \
                int ts_ = idx >> 9, rc_ = idx & 511;                             \
                int row_ = rc_ >> 4, ch_ = rc_ & 15;                             \
                const __nv_bfloat16* src = gsrc_[ts_] +                          \
                    (size_t)((k0_) + row_) * KVDIM + hkv * HD + ch_ * 8;         \
                __nv_bfloat16* dst = (bufp) + ts_ * (ABK * APAD)                 \
                    + row_ * APAD + ch_ * 8;                                     \
                cp_async16s(smem_u32(dst), src);                                 \
            }                                                                    \
        } while (0)

    {
        #pragma unroll
        for (int it = 0; it < 16; ++it) {
            int idx = tid + it * 128;
            int ts = idx >> 10, rc = idx & 1023;
            int row = rc >> 4, ch = rc & 15;
            const __nv_bfloat16* src = (ts ? Qlg : Qhg) +
                (size_t)(q0 + row) * HID + h * HD + ch * 8;
            __nv_bfloat16* dst = (ts ? Ql : Qh) + row * APAD + ch * 8;
            cp_async16s(smem_u32(dst), src);
        }
    }
    int cur = nextv(0, kb_max, q0, n_init, n_local);
    STAGE_KV(KV0, cur * ABK);
    asm volatile("cp.async.commit_group;\n" ::);
    int nxt = nextv(cur + 1, kb_max, q0, n_init, n_local);
    if (nxt <= kb_max) STAGE_KV(KV0 + KVBUF, nxt * ABK);
    asm volatile("cp.async.commit_group;\n" ::);

    uint32_t qfh[8][4], qfl[8][4];
    asm volatile("cp.async.wait_group 1;\n" ::);
    __syncthreads();
    #pragma unroll
    for (int kk = 0; kk < 8; ++kk) {
        const int aoff = (warp * 16 + (lane & 15)) * APAD + kk * 16 + (lane >> 4) * 8;
        ldsm_x4(qfh[kk], Qh + aoff);
        ldsm_x4(qfl[kk], Ql + aoff);
    }

    float o[16][4];
    float m_i[2] = {-1e30f, -1e30f};
    float l_i[2] = {0.f, 0.f};
    #pragma unroll
    for (int nb = 0; nb < 16; nb++)
        #pragma unroll
        for (int j = 0; j < 4; j++) o[nb][j] = 0.f;

    const int   row0  = q0 + warp * 16 + g;
    const float scale = 0.08838834764831845f;
    int buf = 0;

    while (cur <= kb_max) {
        const int k0 = cur * ABK;
        asm volatile("cp.async.wait_group 1;\n" ::);
        __syncthreads();

        __nv_bfloat16* Kh = KV0 + buf * KVBUF;
        __nv_bfloat16* Kl = Kh + ABK * APAD;
        __nv_bfloat16* Vh = Kl + ABK * APAD;
        __nv_bfloat16* Vl = Vh + ABK * APAD;

        float sc[4][4];
        #pragma unroll
        for (int nb = 0; nb < 4; nb++)
            #pragma unroll
            for (int j = 0; j < 4; j++) sc[nb][j] = 0.f;

        #pragma unroll
        for (int kk = 0; kk < 8; ++kk) {
            #pragma unroll
            for (int nbp = 0; nbp < 2; ++nbp) {
                uint32_t kb_h[4], kb_l[4];
                const int boff = (nbp * 16 + (grp >> 1) * 8 + (lane & 7)) * APAD
                               + kk * 16 + (grp & 1) * 8;
                ldsm_x4(kb_h, Kh + boff);
                ldsm_x4(kb_l, Kl + boff);
                mma_bf16(sc[2 * nbp],     qfh[kk], kb_h[0], kb_h[1]);
                mma_bf16(sc[2 * nbp],     qfh[kk], kb_l[0], kb_l[1]);
                mma_bf16(sc[2 * nbp],     qfl[kk], kb_h[0], kb_h[1]);
                mma_bf16(sc[2 * nbp + 1], qfh[kk], kb_h[2], kb_h[3]);
                mma_bf16(sc[2 * nbp + 1], qfh[kk], kb_l[2], kb_l[3]);
                mma_bf16(sc[2 * nbp + 1], qfl[kk], kb_h[2], kb_h[3]);
            }
        }

        float tm0 = -1e30f, tm1 = -1e30f;
        #pragma unroll
        for (int nb = 0; nb < 4; ++nb) {
            int cb = k0 + nb * 8 + 2 * t;
            #pragma unroll
            for (int j = 0; j < 2; ++j) {
                int cc = cb + j;
                bool ok0 = (cc <= row0)     && (cc < n_init || row0 - cc < n_local);
                bool ok1 = (cc <= row0 + 8) && (cc < n_init || row0 + 8 - cc < n_local);
                sc[nb][j]     = ok0 ? sc[nb][j] * scale     : -1e30f;
                sc[nb][2 + j] = ok1 ? sc[nb][2 + j] * scale : -1e30f;
                tm0 = fmaxf(tm0, sc[nb][j]);
                tm1 = fmaxf(tm1, sc[nb][2 + j]);
            }
        }
        tm0 = fmaxf(tm0, __shfl_xor_sync(0xffffffffu, tm0, 1));
        tm0 = fmaxf(tm0, __shfl_xor_sync(0xffffffffu, tm0, 2));
        tm1 = fmaxf(tm1, __shfl_xor_sync(0xffffffffu, tm1, 1));
        tm1 = fmaxf(tm1, __shfl_xor_sync(0xffffffffu, tm1, 2));

        float mn0 = fmaxf(m_i[0], tm0), mn1 = fmaxf(m_i[1], tm1);
        float al0 = __expf(m_i[0] - mn0), al1 = __expf(m_i[1] - mn1);
        float rs0 = 0.f, rs1 = 0.f;
        #pragma unroll
        for (int nb = 0; nb < 4; ++nb) {
            #pragma unroll
            for (int j = 0; j < 2; ++j) {
                float p0 = __expf(sc[nb][j] - mn0);
                float p1 = __expf(sc[nb][2 + j] - mn1);
                sc[nb][j] = p0;  sc[nb][2 + j] = p1;
                rs0 += p0;  rs1 += p1;
            }
        }
        rs0 += __shfl_xor_sync(0xffffffffu, rs0, 1);
        rs0 += __shfl_xor_sync(0xffffffffu, rs0, 2);
        rs1 += __shfl_xor_sync(0xffffffffu, rs1, 1);
        rs1 += __shfl_xor_sync(0xffffffffu, rs1, 2);
        l_i[0] = l_i[0] * al0 + rs0;  m_i[0] = mn0;
        l_i[1] = l_i[1] * al1 + rs1;  m_i[1] = mn1;
        #pragma unroll
        for (int nb = 0; nb < 16; ++nb) {
            o[nb][0] *= al0;  o[nb][1] *= al0;
            o[nb][2] *= al1;  o[nb][3] *= al1;
        }

        uint32_t ph[4][2], pl[4][2];
        #pragma unroll
        for (int nb = 0; nb < 4; ++nb) {
            __nv_bfloat162 h0 = __floats2bfloat162_rn(sc[nb][0], sc[nb][1]);
            __nv_bfloat162 h1 = __floats2bfloat162_rn(sc[nb][2], sc[nb][3]);
            float r0 = sc[nb][0] - __low2float(h0), r1 = sc[nb][1] - __high2float(h0);
            float r2 = sc[nb][2] - __low2float(h1), r3 = sc[nb][3] - __high2float(h1);
            __nv_bfloat162 q0b = __floats2bfloat162_rn(r0, r1);
            __nv_bfloat162 q1b = __floats2bfloat162_rn(r2, r3);
            ph[nb][0] = *(uint32_t*)&h0;  ph[nb][1] = *(uint32_t*)&h1;
            pl[nb][0] = *(uint32_t*)&q0b; pl[nb][1] = *(uint32_t*)&q1b;
        }

        #pragma unroll
        for (int ks = 0; ks < 2; ++ks) {
            uint32_t aH[4] = { ph[2 * ks][0], ph[2 * ks][1],
                               ph[2 * ks + 1][0], ph[2 * ks + 1][1] };
            uint32_t aL[4] = { pl[2 * ks][0], pl[2 * ks][1],
                               pl[2 * ks + 1][0], pl[2 * ks + 1][1] };
            #pragma unroll
            for (int np = 0; np < 8; ++np) {
                uint32_t vh[4], vl[4];
                const int voff = (ks * 16 + (grp & 1) * 8 + (lane & 7)) * APAD
                               + (np * 2 + (grp >> 1)) * 8;
                ldsm_x4_t(vh, Vh + voff);
                ldsm_x4_t(vl, Vl + voff);
                mma_bf16(o[2 * np],     aH, vh[0], vh[1]);
                mma_bf16(o[2 * np],     aH, vl[0], vl[1]);
                mma_bf16(o[2 * np],     aL, vh[0], vh[1]);
                mma_bf16(o[2 * np + 1], aH, vh[2], vh[3]);
                mma_bf16(o[2 * np + 1], aH, vl[2], vl[3]);
                mma_bf16(o[2 * np + 1], aL, vh[2], vh[3]);
            }
        }

        __syncthreads();
        int nn = (nxt <= kb_max) ? nextv(nxt + 1, kb_max, q0, n_init, n_local)
                                 : kb_max + 1;
        if (nn <= kb_max) STAGE_KV(KV0 + buf * KVBUF, nn * ABK);
        asm volatile("cp.async.commit_group;\n" ::);
        cur = nxt;  nxt = nn;  buf ^= 1;
    }

    {
        float inv0 = 1.f / l_i[0], inv1 = 1.f / l_i[1];
        #pragma unroll
        for (int nb = 0; nb < 16; ++nb) {
            o[nb][0] *= inv0;  o[nb][1] *= inv0;
            o[nb][2] *= inv1;  o[nb][3] *= inv1;
        }
        const int pt   = lane & 3;
        const int srcA = (lane & ~3) | (pt >> 1);
        const int srcB = srcA + 2;
        const bool odd = pt & 1;
        const size_t rb = (size_t)(blockIdx.x >> 1);
        const size_t mb = (size_t)((blockIdx.x & 1) * 4 + warp);
        const size_t base = (rb << 17) | (mb << 5) | (size_t)lane;
        #pragma unroll
        for (int nb = 0; nb < 16; ++nb) {
            float s0 = __shfl_sync(0xffffffffu, o[nb][0], srcA);
            float s1 = __shfl_sync(0xffffffffu, o[nb][1], srcA);
            float s2 = __shfl_sync(0xffffffffu, o[nb][2], srcA);
            float s3 = __shfl_sync(0xffffffffu, o[nb][3], srcA);
            float u0 = __shfl_sync(0xffffffffu, o[nb][0], srcB);
            float u1 = __shfl_sync(0xffffffffu, o[nb][1], srcB);
            float u2 = __shfl_sync(0xffffffffu, o[nb][2], srcB);
            float u3 = __shfl_sync(0xffffffffu, o[nb][3], srcB);
            float4 pv;
            pv.x = f2tf_f(odd ? s1 : s0);
            pv.y = f2tf_f(odd ? s3 : s2);
            pv.z = f2tf_f(odd ? u1 : u0);
            pv.w = f2tf_f(odd ? u3 : u2);
            const size_t ksg = (size_t)(h * 8 + (nb >> 1));
            PAout[base + ((size_t)(nb & 1) << 8) + (ksg << 9)] = pv;
        }
    }
}

// ---------------------------------------------------------------------------
extern "C" void kernel_launch(void* const* d_in, const int* in_sizes, int n_in,
                              void* d_out, int out_size) {
    const float* hs = (const float*)d_in[0];
    const float* Wq = (const float*)d_in[1];
    const float* Wk = (const float*)d_in[2];
    const float* Wv = (const float*)d_in[3];
    const float* Wo = (const float*)d_in[4];
    const int* n_init  = (const int*)d_in[5];
    const int* n_local = (const int*)d_in[6];
    float* out = (float*)d_out;

    __nv_bfloat16 *qh, *ql, *kh, *kl, *vh, *vl;
    cudaGetSymbolAddress((void**)&qh, g_qh);  cudaGetSymbolAddress((void**)&ql, g_ql);
    cudaGetSymbolAddress((void**)&kh, g_kh);  cudaGetSymbolAddress((void**)&kl, g_kl);
    cudaGetSymbolAddress((void**)&vh, g_vh);  cudaGetSymbolAddress((void**)&vl, g_vl);
    float4 *pa_hs, *pa_at, *pb_wq, *pb_wk, *pb_wv, *pb_wo;
    cudaGetSymbolAddress((void**)&pa_hs, g_pa_hs);
    cudaGetSymbolAddress((void**)&pa_at, g_pa_at);
    cudaGetSymbolAddress((void**)&pb_wq, g_pb_wq);
    cudaGetSymbolAddress((void**)&pb_wk, g_pb_wk);
    cudaGetSymbolAddress((void**)&pb_wv, g_pb_wv);
    cudaGetSymbolAddress((void**)&pb_wo, g_pb_wo);

    static int attr_set = 0;
    if (!attr_set) {
        cudaFuncSetAttribute(attn_cp,  cudaFuncAttributeMaxDynamicSharedMemorySize, ASMEM2);
        cudaFuncSetAttribute(gemm_pk2, cudaFuncAttributeMaxDynamicSharedMemorySize, PK2_SMEM);
        attr_set = 1;
    }

    pack_all<<<PACK_BLOCKS, 256>>>(hs, Wq, Wk, Wv, Wo,
                                   pa_hs, pb_wq, pb_wk, pb_wv, pb_wo);

    gemm_pk2<<<dim3(24, S_LEN / 128), 256, PK2_SMEM>>>(
        pa_hs,
        pb_wq, 16, nullptr, qh, ql, HID,
        pb_wk, 4,  nullptr, kh, kl, KVDIM,
        pb_wv, 4,  nullptr, vh, vl, KVDIM,
        1);

    attn_cp<<<dim3(S_LEN / ABQ, NH), 128, ASMEM2>>>(qh, ql, kh, kl, vh, vl,
                                                    pa_at, n_init, n_local);

    gemm_pk2<<<dim3(16, S_LEN / 128), 256, PK2_SMEM>>>(
        pa_at,
        pb_wo, 16, out, nullptr, nullptr, HID,
        pb_wo, 0,  out, nullptr, nullptr, HID,
        pb_wo, 0,  out, nullptr, nullptr, HID,
        0);
}

// round 14
// speedup vs baseline: 1.0197x; 1.0197x over previous
#include <cuda_runtime.h>
#include <cuda_bf16.h>
#include <math.h>
#include <stdint.h>

#define S_LEN 2048
#define HID   4096
#define NH    32
#define NKV   8
#define HD    128
#define KVDIM 1024
#define KDIM  4096
#define KS    (KDIM / 16)   // 256 k16 units
#define NS64  (KDIM / 64)   // 64 k64 stages

// ---------------- scratch ----------------
__device__ __align__(16) __nv_bfloat16 g_qh[S_LEN * HID],  g_ql[S_LEN * HID];
__device__ __align__(16) __nv_bfloat16 g_kh[S_LEN * KVDIM], g_kl[S_LEN * KVDIM];
__device__ __align__(16) __nv_bfloat16 g_vh[S_LEN * KVDIM], g_vl[S_LEN * KVDIM];
__device__ float4 g_pa_hs[(S_LEN / 128) * KS * 512];
__device__ float4 g_pa_at[(S_LEN / 128) * KS * 512];
__device__ float4 g_pb_wq[(HID / 128) * KS * 512];
__device__ float4 g_pb_wk[(KVDIM / 128) * KS * 512];
__device__ float4 g_pb_wv[(KVDIM / 128) * KS * 512];
__device__ float4 g_pb_wo[(HID / 128) * KS * 512];

// ---------------- helpers ----------------
__device__ __forceinline__ uint32_t smem_u32(const void* p) {
    uint32_t a;
    asm("{ .reg .u64 t; cvta.to.shared.u64 t, %1; cvt.u32.u64 %0, t; }" : "=r"(a) : "l"(p));
    return a;
}
__device__ __forceinline__ void cp_async16s(uint32_t s, const void* g) {
    asm volatile("cp.async.cg.shared.global [%0], [%1], 16;\n" :: "r"(s), "l"(g));
}
__device__ __forceinline__ float f2tf_f(float x) {
    uint32_t u;
    asm("cvt.rna.tf32.f32 %0, %1;" : "=r"(u) : "f"(x));
    return __uint_as_float(u);
}
__device__ __forceinline__ void mma_tf32(float c[4], const uint32_t a[4],
                                         uint32_t b0, uint32_t b1) {
    asm volatile(
        "mma.sync.aligned.m16n8k8.row.col.f32.tf32.tf32.f32 "
        "{%0,%1,%2,%3},{%4,%5,%6,%7},{%8,%9},{%0,%1,%2,%3};"
        : "+f"(c[0]), "+f"(c[1]), "+f"(c[2]), "+f"(c[3])
        : "r"(a[0]), "r"(a[1]), "r"(a[2]), "r"(a[3]), "r"(b0), "r"(b1));
}

// ---------------------------------------------------------------------------
// Unified pack: tf32-round + fragment-pack for all 5 tensors, smem-staged.
// ---------------------------------------------------------------------------
#define SEG_HS 16
#define SEG_WQ 48
#define SEG_WK 56
#define SEG_WV 64
#define SEG_WO 96
#define PACK_BLOCKS (SEG_WO * 256)

__global__ __launch_bounds__(256) void pack_all(
    const float* __restrict__ hs, const float* __restrict__ Wq,
    const float* __restrict__ Wk, const float* __restrict__ Wv,
    const float* __restrict__ Wo,
    float4* __restrict__ Phs, float4* __restrict__ Pwq,
    float4* __restrict__ Pwk, float4* __restrict__ Pwv,
    float4* __restrict__ Pwo) {
    __shared__ float S[128 * 36];
    const int tid  = threadIdx.x;
    const int tile = blockIdx.x;
    const int ks   = tile & 255;
    const int seg  = tile >> 8;

    const float* X;  float4* P;  int rb, amode;
    if (seg < SEG_HS)      { X = hs; P = Phs; rb = seg;          amode = 1; }
    else if (seg < SEG_WQ) { X = Wq; P = Pwq; rb = seg - SEG_HS; amode = 0; }
    else if (seg < SEG_WK) { X = Wk; P = Pwk; rb = seg - SEG_WQ; amode = 0; }
    else if (seg < SEG_WV) { X = Wv; P = Pwv; rb = seg - SEG_WK; amode = 0; }
    else                   { X = Wo; P = Pwo; rb = seg - SEG_WV; amode = 0; }

    const float* Xb = X + (size_t)rb * 128 * KDIM + ks * 16;
    #pragma unroll
    for (int j = 0; j < 2; ++j) {
        int li = tid + j * 256;
        int row = li >> 2, c4 = (li & 3) << 2;
        float4 v = *(const float4*)(Xb + (size_t)row * KDIM + c4);
        *(float4*)&S[row * 36 + c4] = v;
    }
    __syncthreads();

    float4* Pb = P + (((size_t)rb << 17) | ((size_t)ks << 9));
    #pragma unroll
    for (int j = 0; j < 2; ++j) {
        int oo = tid + j * 256;
        int lane = oo & 31, mb = (oo >> 5) & 7, kk = oo >> 8;
        int g = lane >> 2, t = lane & 3;
        int r = mb * 16 + g, c = kk * 8 + t;
        float a0 = S[r * 36 + c];
        float a1 = S[(r + 8) * 36 + c];
        float a2 = S[r * 36 + c + 4];
        float a3 = S[(r + 8) * 36 + c + 4];
        float4 pv;
        if (amode) pv = make_float4(f2tf_f(a0), f2tf_f(a1), f2tf_f(a2), f2tf_f(a3));
        else       pv = make_float4(f2tf_f(a0), f2tf_f(a2), f2tf_f(a1), f2tf_f(a3));
        Pb[oo] = pv;
    }
}

// ---------------------------------------------------------------------------
// Fragment-packed TF32 GEMM (round-12 version, proven best): CTA 128x256,
// warp 64x64, k=64/stage, 2-stage ring (192 KB).
// split!=0 => bf16 hi/lo split outputs; else f32.
// ---------------------------------------------------------------------------
#define STG_F4  6144                 // A 2048 + B0 2048 + B1 2048 float4
#define STG_BY  (STG_F4 * 16)        // 98304 bytes
#define PK2_SMEM (2 * STG_BY)        // 196608 bytes

__global__ __launch_bounds__(256, 1)
void gemm_pk2(const float4* __restrict__ PA,
              const float4* __restrict__ B0, int nt0, float* C0f,
              __nv_bfloat16* C0h, __nv_bfloat16* C0l, int ld0,
              const float4* __restrict__ B1, int nt1, float* C1f,
              __nv_bfloat16* C1h, __nv_bfloat16* C1l, int ld1,
              const float4* __restrict__ B2, int nt2, float* C2f,
              __nv_bfloat16* C2h, __nv_bfloat16* C2l, int ld2,
              int split) {
    extern __shared__ float4 sm4[];
    const int tid = threadIdx.x, warp = tid >> 5, lane = tid & 31;
    const int g = lane >> 2, t = lane & 3;
    const int wm = warp & 1;
    const int wn = warp >> 1;
    const uint32_t sb = smem_u32(sm4);

    int nt = blockIdx.x;
    const float4* PB;  float* Cf;  __nv_bfloat16 *Ch, *Cl;  int ld;
    if (nt < nt0)            { PB = B0; Cf = C0f; Ch = C0h; Cl = C0l; ld = ld0; }
    else if (nt < nt0 + nt1) { nt -= nt0;       PB = B1; Cf = C1f; Ch = C1h; Cl = C1l; ld = ld1; }
    else                     { nt -= nt0 + nt1; PB = B2; Cf = C2f; Ch = C2h; Cl = C2l; ld = ld2; }

    const size_t abase  = (size_t)blockIdx.y * KS * 512;
    const size_t bbase0 = (size_t)(2 * nt)     * KS * 512;
    const size_t bbase1 = (size_t)(2 * nt + 1) * KS * 512;

    float c[4][8][4];
    #pragma unroll
    for (int mt = 0; mt < 4; mt++)
        #pragma unroll
        for (int ntb = 0; ntb < 8; ntb++)
            #pragma unroll
            for (int i = 0; i < 4; i++) c[mt][ntb][i] = 0.f;

    #define STAGE3(s_)                                                          \
        do {                                                                    \
            const uint32_t db = sb + (uint32_t)((s_) & 1) * STG_BY;             \
            const size_t koff = (size_t)(s_) * 2048;                            \
            _Pragma("unroll")                                                   \
            for (int i_ = 0; i_ < 24; ++i_) {                                   \
                int cix = tid + i_ * 256;                                       \
                const float4* src;                                              \
                if (cix < 2048)       src = PA + abase  + koff + cix;           \
                else if (cix < 4096)  src = PB + bbase0 + koff + (cix - 2048);  \
                else                  src = PB + bbase1 + koff + (cix - 4096);  \
                cp_async16s(db + (uint32_t)cix * 16u, src);                     \
            }                                                                   \
            asm volatile("cp.async.commit_group;\n" ::);                        \
        } while (0)

    STAGE3(0);
    STAGE3(1);

    const int bblk = wn >> 1;
    const int bnp0 = (wn & 1) * 4;

    for (int s = 0; s < NS64; ++s) {
        if (s + 1 < NS64) asm volatile("cp.async.wait_group 1;\n" ::);
        else              asm volatile("cp.async.wait_group 0;\n" ::);
        __syncthreads();

        const float4* As4 = sm4 + (s & 1) * STG_F4;
        const float4* Bs4 = As4 + 2048 + bblk * 2048;
        #pragma unroll
        for (int kk2 = 0; kk2 < 8; ++kk2) {
            const int koffs = (kk2 >> 1) * 512 + (kk2 & 1) * 256;
            float4 av[4], bv[4];
            #pragma unroll
            for (int mt = 0; mt < 4; ++mt)
                av[mt] = As4[koffs + (wm * 4 + mt) * 32 + lane];
            #pragma unroll
            for (int np = 0; np < 4; ++np)
                bv[np] = Bs4[koffs + (bnp0 + np) * 32 + lane];
            #pragma unroll
            for (int mt = 0; mt < 4; ++mt) {
                uint32_t a[4] = { __float_as_uint(av[mt].x), __float_as_uint(av[mt].y),
                                  __float_as_uint(av[mt].z), __float_as_uint(av[mt].w) };
                #pragma unroll
                for (int ntb = 0; ntb < 8; ++ntb) {
                    const float4& b = bv[ntb >> 1];
                    uint32_t b0 = (ntb & 1) ? __float_as_uint(b.z) : __float_as_uint(b.x);
                    uint32_t b1 = (ntb & 1) ? __float_as_uint(b.w) : __float_as_uint(b.y);
                    mma_tf32(c[mt][ntb], a, b0, b1);
                }
            }
        }

        if (s + 2 < NS64) {
            __syncthreads();
            STAGE3(s + 2);
        }
    }

    const int bm = blockIdx.y * 128, bn = nt * 256;
    #pragma unroll
    for (int mt = 0; mt < 4; ++mt) {
        #pragma unroll
        for (int ntb = 0; ntb < 8; ++ntb) {
            const int row = bm + wm * 64 + mt * 16 + g;
            const int col = bn + wn * 64 + ntb * 8 + 2 * t;
            if (!split) {
                *(float2*)&Cf[(size_t)row * ld + col]       = make_float2(c[mt][ntb][0], c[mt][ntb][1]);
                *(float2*)&Cf[(size_t)(row + 8) * ld + col] = make_float2(c[mt][ntb][2], c[mt][ntb][3]);
            } else {
                size_t e0 = (size_t)row * ld + col;
                size_t e1 = (size_t)(row + 8) * ld + col;
                __nv_bfloat162 h0 = __floats2bfloat162_rn(c[mt][ntb][0], c[mt][ntb][1]);
                __nv_bfloat162 h1 = __floats2bfloat162_rn(c[mt][ntb][2], c[mt][ntb][3]);
                __nv_bfloat162 l0 = __floats2bfloat162_rn(c[mt][ntb][0] - __low2float(h0),
                                                          c[mt][ntb][1] - __high2float(h0));
                __nv_bfloat162 l1 = __floats2bfloat162_rn(c[mt][ntb][2] - __low2float(h1),
                                                          c[mt][ntb][3] - __high2float(h1));
                *(__nv_bfloat162*)&Ch[e0] = h0;  *(__nv_bfloat162*)&Cl[e0] = l0;
                *(__nv_bfloat162*)&Ch[e1] = h1;  *(__nv_bfloat162*)&Cl[e1] = l1;
            }
        }
    }
}

// ---------------------------------------------------------------------------
// Attention v4: ABQ=64, ABK=32, 4 warps, 2 CTAs/SM, Q hoisted to registers.
// NEW: Q smem region (exactly KVBUF bytes) reused as a THIRD KV buffer after
// the hoist -> 3-buffer ring, staging pipelined TWO tiles ahead, prefetch
// issued at top of each iteration. Math identical (bit-exact rel_err).
// ---------------------------------------------------------------------------
#define ABQ  64
#define ABK  32
#define APAD 136
#define KVBUF (4 * ABK * APAD)                       // 17408 bf16 = 34816 B
#define ASMEM2 (3 * KVBUF * 2)                       // 104448 bytes

__device__ __forceinline__ void ldsm_x4(uint32_t r[4], const void* p) {
    uint32_t a = smem_u32(p);
    asm volatile("ldmatrix.sync.aligned.m8n8.x4.shared.b16 {%0,%1,%2,%3}, [%4];"
                 : "=r"(r[0]), "=r"(r[1]), "=r"(r[2]), "=r"(r[3]) : "r"(a));
}
__device__ __forceinline__ void ldsm_x4_t(uint32_t r[4], const void* p) {
    uint32_t a = smem_u32(p);
    asm volatile("ldmatrix.sync.aligned.m8n8.x4.trans.shared.b16 {%0,%1,%2,%3}, [%4];"
                 : "=r"(r[0]), "=r"(r[1]), "=r"(r[2]), "=r"(r[3]) : "r"(a));
}
__device__ __forceinline__ void mma_bf16(float c[4], const uint32_t a[4],
                                         uint32_t b0, uint32_t b1) {
    asm volatile(
        "mma.sync.aligned.m16n8k16.row.col.f32.bf16.bf16.f32 "
        "{%0,%1,%2,%3},{%4,%5,%6,%7},{%8,%9},{%0,%1,%2,%3};"
        : "+f"(c[0]), "+f"(c[1]), "+f"(c[2]), "+f"(c[3])
        : "r"(a[0]), "r"(a[1]), "r"(a[2]), "r"(a[3]), "r"(b0), "r"(b1));
}

__device__ __forceinline__ int nextv(int kb, int kb_max, int q0, int n_init, int n_local) {
    while (kb <= kb_max) {
        int k0 = kb * ABK;
        if (!(k0 >= n_init && (q0 - (k0 + ABK - 1)) >= n_local)) break;
        kb++;
    }
    return kb;
}

__global__ __launch_bounds__(128, 2) void attn_cp(
    const __nv_bfloat16* __restrict__ Qhg, const __nv_bfloat16* __restrict__ Qlg,
    const __nv_bfloat16* __restrict__ Khg, const __nv_bfloat16* __restrict__ Klg,
    const __nv_bfloat16* __restrict__ Vhg, const __nv_bfloat16* __restrict__ Vlg,
    float4* __restrict__ PAout,
    const int* __restrict__ n_init_p, const int* __restrict__ n_local_p) {

    extern __shared__ __nv_bfloat16 smb[];
    // buffer b base: smb + b*KVBUF ; buffer 0 doubles as Q staging region
    __nv_bfloat16* Qh = smb;                     // 64*APAD
    __nv_bfloat16* Ql = smb + ABQ * APAD;        // 64*APAD  (Qh+Ql == KVBUF)

    const int h   = blockIdx.y;
    const int q0  = blockIdx.x * ABQ;
    const int hkv = h >> 2;
    const int n_init  = *n_init_p;
    const int n_local = *n_local_p;

    const int tid  = threadIdx.x;
    const int warp = tid >> 5;
    const int lane = tid & 31;
    const int g    = lane >> 2;
    const int t    = lane & 3;
    const int grp  = lane >> 3;

    const int kb_max = (q0 + ABQ - 1) / ABK;

    #define STAGE_KV(bufp, k0_)                                                  \
        do {                                                                     \
            const __nv_bfloat16* gsrc_[4] = { Khg, Klg, Vhg, Vlg };              \
            _Pragma("unroll")                                                    \
            for (int it_ = 0; it_ < 16; ++it_) {                                 \
                int idx = tid + it_ * 128;                                       \
                int ts_ = idx >> 9, rc_ = idx & 511;                             \
                int row_ = rc_ >> 4, ch_ = rc_ & 15;                             \
                const __nv_bfloat16* src = gsrc_[ts_] +                          \
                    (size_t)((k0_) + row_) * KVDIM + hkv * HD + ch_ * 8;         \
                __nv_bfloat16* dst = (bufp) + ts_ * (ABK * APAD)                 \
                    + row_ * APAD + ch_ * 8;                                     \
                cp_async16s(smem_u32(dst), src);                                 \
            }                                                                    \
        } while (0)

    // tile queue (skip-filtered)
    int t0 = nextv(0, kb_max, q0, n_init, n_local);
    int t1 = (t0 <= kb_max) ? nextv(t0 + 1, kb_max, q0, n_init, n_local) : kb_max + 1;
    int t2 = (t1 <= kb_max) ? nextv(t1 + 1, kb_max, q0, n_init, n_local) : kb_max + 1;

    // prologue: group0 = Q + tile t0 (buf1); group1 = tile t1 (buf2)
    {
        #pragma unroll
        for (int it = 0; it < 16; ++it) {
            int idx = tid + it * 128;
            int ts = idx >> 10, rc = idx & 1023;
            int row = rc >> 4, ch = rc & 15;
            const __nv_bfloat16* src = (ts ? Qlg : Qhg) +
                (size_t)(q0 + row) * HID + h * HD + ch * 8;
            __nv_bfloat16* dst = (ts ? Ql : Qh) + row * APAD + ch * 8;
            cp_async16s(smem_u32(dst), src);
        }
    }
    if (t0 <= kb_max) STAGE_KV(smb + 1 * KVBUF, t0 * ABK);
    asm volatile("cp.async.commit_group;\n" ::);
    if (t1 <= kb_max) STAGE_KV(smb + 2 * KVBUF, t1 * ABK);
    asm volatile("cp.async.commit_group;\n" ::);

    // wait group0 (Q + t0), hoist Q into registers
    uint32_t qfh[8][4], qfl[8][4];
    asm volatile("cp.async.wait_group 1;\n" ::);
    __syncthreads();
    #pragma unroll
    for (int kk = 0; kk < 8; ++kk) {
        const int aoff = (warp * 16 + (lane & 15)) * APAD + kk * 16 + (lane >> 4) * 8;
        ldsm_x4(qfh[kk], Qh + aoff);
        ldsm_x4(qfl[kk], Ql + aoff);
    }
    __syncthreads();   // Q reads done before buf0 is overwritten by prefetch

    float o[16][4];
    float m_i[2] = {-1e30f, -1e30f};
    float l_i[2] = {0.f, 0.f};
    #pragma unroll
    for (int nb = 0; nb < 16; nb++)
        #pragma unroll
        for (int j = 0; j < 4; j++) o[nb][j] = 0.f;

    const int   row0  = q0 + warp * 16 + g;
    const float scale = 0.08838834764831845f;
    int ib = 1;   // buffer holding t0

    while (t0 <= kb_max) {
        const int k0 = t0 * ABK;

        // prefetch tile t2 two-ahead into buffer (ib+2)%3 (freed last iter)
        if (t2 <= kb_max) STAGE_KV(smb + (uint32_t)((ib + 2) % 3) * KVBUF, t2 * ABK);
        asm volatile("cp.async.commit_group;\n" ::);

        __nv_bfloat16* Kh = smb + (uint32_t)ib * KVBUF;
        __nv_bfloat16* Kl = Kh + ABK * APAD;
        __nv_bfloat16* Vh = Kl + ABK * APAD;
        __nv_bfloat16* Vl = Vh + ABK * APAD;

        // ---- S = Q @ K^T (3-term split), Q from registers ----
        float sc[4][4];
        #pragma unroll
        for (int nb = 0; nb < 4; nb++)
            #pragma unroll
            for (int j = 0; j < 4; j++) sc[nb][j] = 0.f;

        #pragma unroll
        for (int kk = 0; kk < 8; ++kk) {
            #pragma unroll
            for (int nbp = 0; nbp < 2; ++nbp) {
                uint32_t kb_h[4], kb_l[4];
                const int boff = (nbp * 16 + (grp >> 1) * 8 + (lane & 7)) * APAD
                               + kk * 16 + (grp & 1) * 8;
                ldsm_x4(kb_h, Kh + boff);
                ldsm_x4(kb_l, Kl + boff);
                mma_bf16(sc[2 * nbp],     qfh[kk], kb_h[0], kb_h[1]);
                mma_bf16(sc[2 * nbp],     qfh[kk], kb_l[0], kb_l[1]);
                mma_bf16(sc[2 * nbp],     qfl[kk], kb_h[0], kb_h[1]);
                mma_bf16(sc[2 * nbp + 1], qfh[kk], kb_h[2], kb_h[3]);
                mma_bf16(sc[2 * nbp + 1], qfh[kk], kb_l[2], kb_l[3]);
                mma_bf16(sc[2 * nbp + 1], qfl[kk], kb_h[2], kb_h[3]);
            }
        }

        // ---- mask + online softmax ----
        float tm0 = -1e30f, tm1 = -1e30f;
        #pragma unroll
        for (int nb = 0; nb < 4; ++nb) {
            int cb = k0 + nb * 8 + 2 * t;
            #pragma unroll
            for (int j = 0; j < 2; ++j) {
                int cc = cb + j;
                bool ok0 = (cc <= row0)     && (cc < n_init || row0 - cc < n_local);
                bool ok1 = (cc <= row0 + 8) && (cc < n_init || row0 + 8 - cc < n_local);
                sc[nb][j]     = ok0 ? sc[nb][j] * scale     : -1e30f;
                sc[nb][2 + j] = ok1 ? sc[nb][2 + j] * scale : -1e30f;
                tm0 = fmaxf(tm0, sc[nb][j]);
                tm1 = fmaxf(tm1, sc[nb][2 + j]);
            }
        }
        tm0 = fmaxf(tm0, __shfl_xor_sync(0xffffffffu, tm0, 1));
        tm0 = fmaxf(tm0, __shfl_xor_sync(0xffffffffu, tm0, 2));
        tm1 = fmaxf(tm1, __shfl_xor_sync(0xffffffffu, tm1, 1));
        tm1 = fmaxf(tm1, __shfl_xor_sync(0xffffffffu, tm1, 2));

        float mn0 = fmaxf(m_i[0], tm0), mn1 = fmaxf(m_i[1], tm1);
        float al0 = __expf(m_i[0] - mn0), al1 = __expf(m_i[1] - mn1);
        float rs0 = 0.f, rs1 = 0.f;
        #pragma unroll
        for (int nb = 0; nb < 4; ++nb) {
            #pragma unroll
            for (int j = 0; j < 2; ++j) {
                float p0 = __expf(sc[nb][j] - mn0);
                float p1 = __expf(sc[nb][2 + j] - mn1);
                sc[nb][j] = p0;  sc[nb][2 + j] = p1;
                rs0 += p0;  rs1 += p1;
            }
        }
        rs0 += __shfl_xor_sync(0xffffffffu, rs0, 1);
        rs0 += __shfl_xor_sync(0xffffffffu, rs0, 2);
        rs1 += __shfl_xor_sync(0xffffffffu, rs1, 1);
        rs1 += __shfl_xor_sync(0xffffffffu, rs1, 2);
        l_i[0] = l_i[0] * al0 + rs0;  m_i[0] = mn0;
        l_i[1] = l_i[1] * al1 + rs1;  m_i[1] = mn1;
        #pragma unroll
        for (int nb = 0; nb < 16; ++nb) {
            o[nb][0] *= al0;  o[nb][1] *= al0;
            o[nb][2] *= al1;  o[nb][3] *= al1;
        }

        // ---- pack P fragments (hi/lo) from registers ----
        uint32_t ph[4][2], pl[4][2];
        #pragma unroll
        for (int nb = 0; nb < 4; ++nb) {
            __nv_bfloat162 h0 = __floats2bfloat162_rn(sc[nb][0], sc[nb][1]);
            __nv_bfloat162 h1 = __floats2bfloat162_rn(sc[nb][2], sc[nb][3]);
            float r0 = sc[nb][0] - __low2float(h0), r1 = sc[nb][1] - __high2float(h0);
            float r2 = sc[nb][2] - __low2float(h1), r3 = sc[nb][3] - __high2float(h1);
            __nv_bfloat162 q0b = __floats2bfloat162_rn(r0, r1);
            __nv_bfloat162 q1b = __floats2bfloat162_rn(r2, r3);
            ph[nb][0] = *(uint32_t*)&h0;  ph[nb][1] = *(uint32_t*)&h1;
            pl[nb][0] = *(uint32_t*)&q0b; pl[nb][1] = *(uint32_t*)&q1b;
        }

        // ---- O += P @ V (3-term split) ----
        #pragma unroll
        for (int ks = 0; ks < 2; ++ks) {
            uint32_t aH[4] = { ph[2 * ks][0], ph[2 * ks][1],
                               ph[2 * ks + 1][0], ph[2 * ks + 1][1] };
            uint32_t aL[4] = { pl[2 * ks][0], pl[2 * ks][1],
                               pl[2 * ks + 1][0], pl[2 * ks + 1][1] };
            #pragma unroll
            for (int np = 0; np < 8; ++np) {
                uint32_t vh[4], vl[4];
                const int voff = (ks * 16 + (grp & 1) * 8 + (lane & 7)) * APAD
                               + (np * 2 + (grp >> 1)) * 8;
                ldsm_x4_t(vh, Vh + voff);
                ldsm_x4_t(vl, Vl + voff);
                mma_bf16(o[2 * np],     aH, vh[0], vh[1]);
                mma_bf16(o[2 * np],     aH, vl[0], vl[1]);
                mma_bf16(o[2 * np],     aL, vh[0], vh[1]);
                mma_bf16(o[2 * np + 1], aH, vh[2], vh[3]);
                mma_bf16(o[2 * np + 1], aH, vl[2], vl[3]);
                mma_bf16(o[2 * np + 1], aL, vh[2], vh[3]);
            }
        }

        // advance queue
        t0 = t1;  t1 = t2;
        t2 = (t1 <= kb_max) ? nextv(t1 + 1, kb_max, q0, n_init, n_local) : kb_max + 1;
        ib = (ib + 1) % 3;
        if (t0 <= kb_max) {
            asm volatile("cp.async.wait_group 1;\n" ::);  // next tile's group done
            __syncthreads();                               // all warps past old buffer
        }
    }

    // ---- fused epilogue: normalize + butterfly to packed-A fragment layout ----
    {
        float inv0 = 1.f / l_i[0], inv1 = 1.f / l_i[1];
        #pragma unroll
        for (int nb = 0; nb < 16; ++nb) {
            o[nb][0] *= inv0;  o[nb][1] *= inv0;
            o[nb][2] *= inv1;  o[nb][3] *= inv1;
        }
        const int pt   = lane & 3;
        const int srcA = (lane & ~3) | (pt >> 1);
        const int srcB = srcA + 2;
        const bool odd = pt & 1;
        const size_t rb = (size_t)(blockIdx.x >> 1);
        const size_t mb = (size_t)((blockIdx.x & 1) * 4 + warp);
        const size_t base = (rb << 17) | (mb << 5) | (size_t)lane;
        #pragma unroll
        for (int nb = 0; nb < 16; ++nb) {
            float s0 = __shfl_sync(0xffffffffu, o[nb][0], srcA);
            float s1 = __shfl_sync(0xffffffffu, o[nb][1], srcA);
            float s2 = __shfl_sync(0xffffffffu, o[nb][2], srcA);
            float s3 = __shfl_sync(0xffffffffu, o[nb][3], srcA);
            float u0 = __shfl_sync(0xffffffffu, o[nb][0], srcB);
            float u1 = __shfl_sync(0xffffffffu, o[nb][1], srcB);
            float u2 = __shfl_sync(0xffffffffu, o[nb][2], srcB);
            float u3 = __shfl_sync(0xffffffffu, o[nb][3], srcB);
            float4 pv;
            pv.x = f2tf_f(odd ? s1 : s0);
            pv.y = f2tf_f(odd ? s3 : s2);
            pv.z = f2tf_f(odd ? u1 : u0);
            pv.w = f2tf_f(odd ? u3 : u2);
            const size_t ksg = (size_t)(h * 8 + (nb >> 1));
            PAout[base + ((size_t)(nb & 1) << 8) + (ksg << 9)] = pv;
        }
    }
}

// ---------------------------------------------------------------------------
extern "C" void kernel_launch(void* const* d_in, const int* in_sizes, int n_in,
                              void* d_out, int out_size) {
    const float* hs = (const float*)d_in[0];
    const float* Wq = (const float*)d_in[1];
    const float* Wk = (const float*)d_in[2];
    const float* Wv = (const float*)d_in[3];
    const float* Wo = (const float*)d_in[4];
    const int* n_init  = (const int*)d_in[5];
    const int* n_local = (const int*)d_in[6];
    float* out = (float*)d_out;

    __nv_bfloat16 *qh, *ql, *kh, *kl, *vh, *vl;
    cudaGetSymbolAddress((void**)&qh, g_qh);  cudaGetSymbolAddress((void**)&ql, g_ql);
    cudaGetSymbolAddress((void**)&kh, g_kh);  cudaGetSymbolAddress((void**)&kl, g_kl);
    cudaGetSymbolAddress((void**)&vh, g_vh);  cudaGetSymbolAddress((void**)&vl, g_vl);
    float4 *pa_hs, *pa_at, *pb_wq, *pb_wk, *pb_wv, *pb_wo;
    cudaGetSymbolAddress((void**)&pa_hs, g_pa_hs);
    cudaGetSymbolAddress((void**)&pa_at, g_pa_at);
    cudaGetSymbolAddress((void**)&pb_wq, g_pb_wq);
    cudaGetSymbolAddress((void**)&pb_wk, g_pb_wk);
    cudaGetSymbolAddress((void**)&pb_wv, g_pb_wv);
    cudaGetSymbolAddress((void**)&pb_wo, g_pb_wo);

    static int attr_set = 0;
    if (!attr_set) {
        cudaFuncSetAttribute(attn_cp,  cudaFuncAttributeMaxDynamicSharedMemorySize, ASMEM2);
        cudaFuncSetAttribute(gemm_pk2, cudaFuncAttributeMaxDynamicSharedMemorySize, PK2_SMEM);
        attr_set = 1;
    }

    pack_all<<<PACK_BLOCKS, 256>>>(hs, Wq, Wk, Wv, Wo,
                                   pa_hs, pb_wq, pb_wk, pb_wv, pb_wo);

    gemm_pk2<<<dim3(24, S_LEN / 128), 256, PK2_SMEM>>>(
        pa_hs,
        pb_wq, 16, nullptr, qh, ql, HID,
        pb_wk, 4,  nullptr, kh, kl, KVDIM,
        pb_wv, 4,  nullptr, vh, vl, KVDIM,
        1);

    attn_cp<<<dim3(S_LEN / ABQ, NH), 128, ASMEM2>>>(qh, ql, kh, kl, vh, vl,
                                                    pa_at, n_init, n_local);

    gemm_pk2<<<dim3(16, S_LEN / 128), 256, PK2_SMEM>>>(
        pa_at,
        pb_wo, 16, out, nullptr, nullptr, HID,
        pb_wo, 0,  out, nullptr, nullptr, HID,
        pb_wo, 0,  out, nullptr, nullptr, HID,
        0);
}

// round 15
// speedup vs baseline: 1.5537x; 1.5237x over previous
#include <cuda_runtime.h>
#include <cuda_bf16.h>
#include <cuda_fp16.h>
#include <math.h>
#include <stdint.h>

#define S_LEN 2048
#define HID   4096
#define NH    32
#define NKV   8
#define HD    128
#define KVDIM 1024
#define KDIM  4096
#define K16S  (KDIM / 16)    // 256 k16 units
#define NS128 (KDIM / 128)   // 32 k128 stages

// ---------------- scratch ----------------
// fp16 fragment-packed operands: per (blk128, k16): 8x32 float4
__device__ __align__(16) __nv_bfloat16 g_qh[S_LEN * HID],  g_ql[S_LEN * HID];
__device__ __align__(16) __nv_bfloat16 g_kh[S_LEN * KVDIM], g_kl[S_LEN * KVDIM];
__device__ __align__(16) __nv_bfloat16 g_vh[S_LEN * KVDIM], g_vl[S_LEN * KVDIM];
__device__ float4 g_pa_hs[(S_LEN / 128) * K16S * 256];   // 16 MB
__device__ float4 g_pa_at[(S_LEN / 128) * K16S * 256];
__device__ float4 g_pb_wq[(HID / 128) * K16S * 256];     // 32 MB
__device__ float4 g_pb_wk[(KVDIM / 128) * K16S * 256];
__device__ float4 g_pb_wv[(KVDIM / 128) * K16S * 256];
__device__ float4 g_pb_wo[(HID / 128) * K16S * 256];

// ---------------- helpers ----------------
__device__ __forceinline__ uint32_t smem_u32(const void* p) {
    uint32_t a;
    asm("{ .reg .u64 t; cvta.to.shared.u64 t, %1; cvt.u32.u64 %0, t; }" : "=r"(a) : "l"(p));
    return a;
}
__device__ __forceinline__ void cp_async16s(uint32_t s, const void* g) {
    asm volatile("cp.async.cg.shared.global [%0], [%1], 16;\n" :: "r"(s), "l"(g));
}
__device__ __forceinline__ uint32_t pkh(float a, float b) {
    __half2 h = __floats2half2_rn(a, b);
    return *(uint32_t*)&h;
}
__device__ __forceinline__ void mma_fp16(float c[4], const uint32_t a[4],
                                         uint32_t b0, uint32_t b1) {
    asm volatile(
        "mma.sync.aligned.m16n8k16.row.col.f32.f16.f16.f32 "
        "{%0,%1,%2,%3},{%4,%5,%6,%7},{%8,%9},{%0,%1,%2,%3};"
        : "+f"(c[0]), "+f"(c[1]), "+f"(c[2]), "+f"(c[3])
        : "r"(a[0]), "r"(a[1]), "r"(a[2]), "r"(a[3]), "r"(b0), "r"(b1));
}

// ---------------------------------------------------------------------------
// Unified pack: fp16 fragment-pack for all 5 tensors, smem-staged.
// Block = one (tensor, blk128, k16) 128x16 f32 tile; writes 256 float4.
// A-mode float4 = {a0,a1,a2,a3} fp16x2 regs of m16n8k16 A-frag.
// B-mode float4 = {b0,b1 of n8 blk 2p, b0,b1 of n8 blk 2p+1}.
// ---------------------------------------------------------------------------
#define SEG_HS 16
#define SEG_WQ 48
#define SEG_WK 56
#define SEG_WV 64
#define SEG_WO 96
#define PACK_BLOCKS (SEG_WO * 256)

__global__ __launch_bounds__(256) void pack_all(
    const float* __restrict__ hs, const float* __restrict__ Wq,
    const float* __restrict__ Wk, const float* __restrict__ Wv,
    const float* __restrict__ Wo,
    float4* __restrict__ Phs, float4* __restrict__ Pwq,
    float4* __restrict__ Pwk, float4* __restrict__ Pwv,
    float4* __restrict__ Pwo) {
    __shared__ float S[128 * 36];
    const int tid  = threadIdx.x;
    const int tile = blockIdx.x;
    const int ks   = tile & 255;
    const int seg  = tile >> 8;

    const float* X;  float4* P;  int rb, amode;
    if (seg < SEG_HS)      { X = hs; P = Phs; rb = seg;          amode = 1; }
    else if (seg < SEG_WQ) { X = Wq; P = Pwq; rb = seg - SEG_HS; amode = 0; }
    else if (seg < SEG_WK) { X = Wk; P = Pwk; rb = seg - SEG_WQ; amode = 0; }
    else if (seg < SEG_WV) { X = Wv; P = Pwv; rb = seg - SEG_WK; amode = 0; }
    else                   { X = Wo; P = Pwo; rb = seg - SEG_WV; amode = 0; }

    const float* Xb = X + (size_t)rb * 128 * KDIM + ks * 16;
    #pragma unroll
    for (int j = 0; j < 2; ++j) {
        int li = tid + j * 256;
        int row = li >> 2, c4 = (li & 3) << 2;
        float4 v = *(const float4*)(Xb + (size_t)row * KDIM + c4);
        *(float4*)&S[row * 36 + c4] = v;
    }
    __syncthreads();

    const int lane = tid & 31, blk = tid >> 5;
    const int g = lane >> 2, t = lane & 3;
    float4 pv;
    if (amode) {
        int r = blk * 16 + g;
        pv.x = __uint_as_float(pkh(S[r * 36 + 2 * t],       S[r * 36 + 2 * t + 1]));
        pv.y = __uint_as_float(pkh(S[(r + 8) * 36 + 2 * t], S[(r + 8) * 36 + 2 * t + 1]));
        pv.z = __uint_as_float(pkh(S[r * 36 + 2 * t + 8],   S[r * 36 + 2 * t + 9]));
        pv.w = __uint_as_float(pkh(S[(r + 8) * 36 + 2 * t + 8], S[(r + 8) * 36 + 2 * t + 9]));
    } else {
        int c0 = blk * 16 + g, c1 = c0 + 8;     // S[n][k]: b = {B[k][n]}
        pv.x = __uint_as_float(pkh(S[c0 * 36 + 2 * t],     S[c0 * 36 + 2 * t + 1]));
        pv.y = __uint_as_float(pkh(S[c0 * 36 + 2 * t + 8], S[c0 * 36 + 2 * t + 9]));
        pv.z = __uint_as_float(pkh(S[c1 * 36 + 2 * t],     S[c1 * 36 + 2 * t + 1]));
        pv.w = __uint_as_float(pkh(S[c1 * 36 + 2 * t + 8], S[c1 * 36 + 2 * t + 9]));
    }
    P[(((size_t)rb << 8 | ks) << 8) + tid] = pv;
}

// ---------------------------------------------------------------------------
// Fragment-packed FP16 GEMM: CTA 128x256, warp 64x64, k=128/stage,
// 2-stage ring (192 KB). m16n8k16 fp16 with fp32 accum (same mantissa as tf32).
// split!=0 => bf16 hi/lo split outputs; else f32.
// ---------------------------------------------------------------------------
#define STG_F4  6144                 // A 2048 + B0 2048 + B1 2048 float4
#define STG_BY  (STG_F4 * 16)        // 98304 bytes
#define PK2_SMEM (2 * STG_BY)        // 196608 bytes

__global__ __launch_bounds__(256, 1)
void gemm_pk2(const float4* __restrict__ PA,
              const float4* __restrict__ B0, int nt0, float* C0f,
              __nv_bfloat16* C0h, __nv_bfloat16* C0l, int ld0,
              const float4* __restrict__ B1, int nt1, float* C1f,
              __nv_bfloat16* C1h, __nv_bfloat16* C1l, int ld1,
              const float4* __restrict__ B2, int nt2, float* C2f,
              __nv_bfloat16* C2h, __nv_bfloat16* C2l, int ld2,
              int split) {
    extern __shared__ float4 sm4[];
    const int tid = threadIdx.x, warp = tid >> 5, lane = tid & 31;
    const int g = lane >> 2, t = lane & 3;
    const int wm = warp & 1;
    const int wn = warp >> 1;
    const uint32_t sb = smem_u32(sm4);

    int nt = blockIdx.x;
    const float4* PB;  float* Cf;  __nv_bfloat16 *Ch, *Cl;  int ld;
    if (nt < nt0)            { PB = B0; Cf = C0f; Ch = C0h; Cl = C0l; ld = ld0; }
    else if (nt < nt0 + nt1) { nt -= nt0;       PB = B1; Cf = C1f; Ch = C1h; Cl = C1l; ld = ld1; }
    else                     { nt -= nt0 + nt1; PB = B2; Cf = C2f; Ch = C2h; Cl = C2l; ld = ld2; }

    const size_t abase  = (size_t)blockIdx.y << 16;          // 256 k16 * 256 f4
    const size_t bbase0 = (size_t)(2 * nt)     << 16;
    const size_t bbase1 = (size_t)(2 * nt + 1) << 16;

    float c[4][8][4];
    #pragma unroll
    for (int mt = 0; mt < 4; mt++)
        #pragma unroll
        for (int ntb = 0; ntb < 8; ntb++)
            #pragma unroll
            for (int i = 0; i < 4; i++) c[mt][ntb][i] = 0.f;

    // stage s covers k16 units [8s, 8s+8): 2048 f4 per operand block
    #define STAGE3(s_)                                                          \
        do {                                                                    \
            const uint32_t db = sb + (uint32_t)((s_) & 1) * STG_BY;             \
            const size_t koff = (size_t)(s_) * 2048;                            \
            _Pragma("unroll")                                                   \
            for (int i_ = 0; i_ < 24; ++i_) {                                   \
                int cix = tid + i_ * 256;                                       \
                const float4* src;                                              \
                if (cix < 2048)       src = PA + abase  + koff + cix;           \
                else if (cix < 4096)  src = PB + bbase0 + koff + (cix - 2048);  \
                else                  src = PB + bbase1 + koff + (cix - 4096);  \
                cp_async16s(db + (uint32_t)cix * 16u, src);                     \
            }                                                                   \
            asm volatile("cp.async.commit_group;\n" ::);                        \
        } while (0)

    STAGE3(0);
    STAGE3(1);

    const int bblk = wn >> 1;
    const int bnp0 = (wn & 1) * 4;

    for (int s = 0; s < NS128; ++s) {
        if (s + 1 < NS128) asm volatile("cp.async.wait_group 1;\n" ::);
        else               asm volatile("cp.async.wait_group 0;\n" ::);
        __syncthreads();

        const float4* As4 = sm4 + (s & 1) * STG_F4;
        const float4* Bs4 = As4 + 2048 + bblk * 2048;
        #pragma unroll
        for (int kk = 0; kk < 8; ++kk) {        // 8 x k16 within k128 stage
            float4 av[4], bv[4];
            #pragma unroll
            for (int mt = 0; mt < 4; ++mt)
                av[mt] = As4[kk * 256 + (wm * 4 + mt) * 32 + lane];
            #pragma unroll
            for (int p = 0; p < 4; ++p)
                bv[p] = Bs4[kk * 256 + (bnp0 + p) * 32 + lane];
            #pragma unroll
            for (int mt = 0; mt < 4; ++mt) {
                uint32_t a[4] = { __float_as_uint(av[mt].x), __float_as_uint(av[mt].y),
                                  __float_as_uint(av[mt].z), __float_as_uint(av[mt].w) };
                #pragma unroll
                for (int p = 0; p < 4; ++p) {
                    mma_fp16(c[mt][2 * p],     a, __float_as_uint(bv[p].x), __float_as_uint(bv[p].y));
                    mma_fp16(c[mt][2 * p + 1], a, __float_as_uint(bv[p].z), __float_as_uint(bv[p].w));
                }
            }
        }

        if (s + 2 < NS128) {
            __syncthreads();
            STAGE3(s + 2);
        }
    }

    const int bm = blockIdx.y * 128, bn = nt * 256;
    #pragma unroll
    for (int mt = 0; mt < 4; ++mt) {
        #pragma unroll
        for (int ntb = 0; ntb < 8; ++ntb) {
            const int row = bm + wm * 64 + mt * 16 + g;
            const int col = bn + wn * 64 + ntb * 8 + 2 * t;
            if (!split) {
                *(float2*)&Cf[(size_t)row * ld + col]       = make_float2(c[mt][ntb][0], c[mt][ntb][1]);
                *(float2*)&Cf[(size_t)(row + 8) * ld + col] = make_float2(c[mt][ntb][2], c[mt][ntb][3]);
            } else {
                size_t e0 = (size_t)row * ld + col;
                size_t e1 = (size_t)(row + 8) * ld + col;
                __nv_bfloat162 h0 = __floats2bfloat162_rn(c[mt][ntb][0], c[mt][ntb][1]);
                __nv_bfloat162 h1 = __floats2bfloat162_rn(c[mt][ntb][2], c[mt][ntb][3]);
                __nv_bfloat162 l0 = __floats2bfloat162_rn(c[mt][ntb][0] - __low2float(h0),
                                                          c[mt][ntb][1] - __high2float(h0));
                __nv_bfloat162 l1 = __floats2bfloat162_rn(c[mt][ntb][2] - __low2float(h1),
                                                          c[mt][ntb][3] - __high2float(h1));
                *(__nv_bfloat162*)&Ch[e0] = h0;  *(__nv_bfloat162*)&Cl[e0] = l0;
                *(__nv_bfloat162*)&Ch[e1] = h1;  *(__nv_bfloat162*)&Cl[e1] = l1;
            }
        }
    }
}

// ---------------------------------------------------------------------------
// Attention (round-14 kernel): ABQ=64, ABK=32, 4 warps, 2 CTAs/SM,
// Q hoisted to registers, 3-buffer KV ring pipelined 2 ahead.
// Epilogue now writes fp16 packed-A fragments (no shuffles: layouts align).
// ---------------------------------------------------------------------------
#define ABQ  64
#define ABK  32
#define APAD 136
#define KVBUF (4 * ABK * APAD)
#define ASMEM2 (3 * KVBUF * 2)

__device__ __forceinline__ void ldsm_x4(uint32_t r[4], const void* p) {
    uint32_t a = smem_u32(p);
    asm volatile("ldmatrix.sync.aligned.m8n8.x4.shared.b16 {%0,%1,%2,%3}, [%4];"
                 : "=r"(r[0]), "=r"(r[1]), "=r"(r[2]), "=r"(r[3]) : "r"(a));
}
__device__ __forceinline__ void ldsm_x4_t(uint32_t r[4], const void* p) {
    uint32_t a = smem_u32(p);
    asm volatile("ldmatrix.sync.aligned.m8n8.x4.trans.shared.b16 {%0,%1,%2,%3}, [%4];"
                 : "=r"(r[0]), "=r"(r[1]), "=r"(r[2]), "=r"(r[3]) : "r"(a));
}
__device__ __forceinline__ void mma_bf16(float c[4], const uint32_t a[4],
                                         uint32_t b0, uint32_t b1) {
    asm volatile(
        "mma.sync.aligned.m16n8k16.row.col.f32.bf16.bf16.f32 "
        "{%0,%1,%2,%3},{%4,%5,%6,%7},{%8,%9},{%0,%1,%2,%3};"
        : "+f"(c[0]), "+f"(c[1]), "+f"(c[2]), "+f"(c[3])
        : "r"(a[0]), "r"(a[1]), "r"(a[2]), "r"(a[3]), "r"(b0), "r"(b1));
}

__device__ __forceinline__ int nextv(int kb, int kb_max, int q0, int n_init, int n_local) {
    while (kb <= kb_max) {
        int k0 = kb * ABK;
        if (!(k0 >= n_init && (q0 - (k0 + ABK - 1)) >= n_local)) break;
        kb++;
    }
    return kb;
}

__global__ __launch_bounds__(128, 2) void attn_cp(
    const __nv_bfloat16* __restrict__ Qhg, const __nv_bfloat16* __restrict__ Qlg,
    const __nv_bfloat16* __restrict__ Khg, const __nv_bfloat16* __restrict__ Klg,
    const __nv_bfloat16* __restrict__ Vhg, const __nv_bfloat16* __restrict__ Vlg,
    float4* __restrict__ PAout,
    const int* __restrict__ n_init_p, const int* __restrict__ n_local_p) {

    extern __shared__ __nv_bfloat16 smb[];
    __nv_bfloat16* Qh = smb;
    __nv_bfloat16* Ql = smb + ABQ * APAD;

    const int h   = blockIdx.y;
    const int q0  = blockIdx.x * ABQ;
    const int hkv = h >> 2;
    const int n_init  = *n_init_p;
    const int n_local = *n_local_p;

    const int tid  = threadIdx.x;
    const int warp = tid >> 5;
    const int lane = tid & 31;
    const int g    = lane >> 2;
    const int t    = lane & 3;
    const int grp  = lane >> 3;

    const int kb_max = (q0 + ABQ - 1) / ABK;

    #define STAGE_KV(bufp, k0_)                                                  \
        do {                                                                     \
            const __nv_bfloat16* gsrc_[4] = { Khg, Klg, Vhg, Vlg };              \
            _Pragma("unroll")                                                    \
            for (int it_ = 0; it_ < 16; ++it_) {                                 \
                int idx = tid + it_ * 128;                                       \
                int ts_ = idx >> 9, rc_ = idx & 511;                             \
                int row_ = rc_ >> 4, ch_ = rc_ & 15;                             \
                const __nv_bfloat16* src = gsrc_[ts_] +                          \
                    (size_t)((k0_) + row_) * KVDIM + hkv * HD + ch_ * 8;         \
                __nv_bfloat16* dst = (bufp) + ts_ * (ABK * APAD)                 \
                    + row_ * APAD + ch_ * 8;                                     \
                cp_async16s(smem_u32(dst), src);                                 \
            }                                                                    \
        } while (0)

    int t0 = nextv(0, kb_max, q0, n_init, n_local);
    int t1 = (t0 <= kb_max) ? nextv(t0 + 1, kb_max, q0, n_init, n_local) : kb_max + 1;
    int t2 = (t1 <= kb_max) ? nextv(t1 + 1, kb_max, q0, n_init, n_local) : kb_max + 1;

    {
        #pragma unroll
        for (int it = 0; it < 16; ++it) {
            int idx = tid + it * 128;
            int ts = idx >> 10, rc = idx & 1023;
            int row = rc >> 4, ch = rc & 15;
            const __nv_bfloat16* src = (ts ? Qlg : Qhg) +
                (size_t)(q0 + row) * HID + h * HD + ch * 8;
            __nv_bfloat16* dst = (ts ? Ql : Qh) + row * APAD + ch * 8;
            cp_async16s(smem_u32(dst), src);
        }
    }
    if (t0 <= kb_max) STAGE_KV(smb + 1 * KVBUF, t0 * ABK);
    asm volatile("cp.async.commit_group;\n" ::);
    if (t1 <= kb_max) STAGE_KV(smb + 2 * KVBUF, t1 * ABK);
    asm volatile("cp.async.commit_group;\n" ::);

    uint32_t qfh[8][4], qfl[8][4];
    asm volatile("cp.async.wait_group 1;\n" ::);
    __syncthreads();
    #pragma unroll
    for (int kk = 0; kk < 8; ++kk) {
        const int aoff = (warp * 16 + (lane & 15)) * APAD + kk * 16 + (lane >> 4) * 8;
        ldsm_x4(qfh[kk], Qh + aoff);
        ldsm_x4(qfl[kk], Ql + aoff);
    }
    __syncthreads();

    float o[16][4];
    float m_i[2] = {-1e30f, -1e30f};
    float l_i[2] = {0.f, 0.f};
    #pragma unroll
    for (int nb = 0; nb < 16; nb++)
        #pragma unroll
        for (int j = 0; j < 4; j++) o[nb][j] = 0.f;

    const int   row0  = q0 + warp * 16 + g;
    const float scale = 0.08838834764831845f;
    int ib = 1;

    while (t0 <= kb_max) {
        const int k0 = t0 * ABK;

        if (t2 <= kb_max) STAGE_KV(smb + (uint32_t)((ib + 2) % 3) * KVBUF, t2 * ABK);
        asm volatile("cp.async.commit_group;\n" ::);

        __nv_bfloat16* Kh = smb + (uint32_t)ib * KVBUF;
        __nv_bfloat16* Kl = Kh + ABK * APAD;
        __nv_bfloat16* Vh = Kl + ABK * APAD;
        __nv_bfloat16* Vl = Vh + ABK * APAD;

        float sc[4][4];
        #pragma unroll
        for (int nb = 0; nb < 4; nb++)
            #pragma unroll
            for (int j = 0; j < 4; j++) sc[nb][j] = 0.f;

        #pragma unroll
        for (int kk = 0; kk < 8; ++kk) {
            #pragma unroll
            for (int nbp = 0; nbp < 2; ++nbp) {
                uint32_t kb_h[4], kb_l[4];
                const int boff = (nbp * 16 + (grp >> 1) * 8 + (lane & 7)) * APAD
                               + kk * 16 + (grp & 1) * 8;
                ldsm_x4(kb_h, Kh + boff);
                ldsm_x4(kb_l, Kl + boff);
                mma_bf16(sc[2 * nbp],     qfh[kk], kb_h[0], kb_h[1]);
                mma_bf16(sc[2 * nbp],     qfh[kk], kb_l[0], kb_l[1]);
                mma_bf16(sc[2 * nbp],     qfl[kk], kb_h[0], kb_h[1]);
                mma_bf16(sc[2 * nbp + 1], qfh[kk], kb_h[2], kb_h[3]);
                mma_bf16(sc[2 * nbp + 1], qfh[kk], kb_l[2], kb_l[3]);
                mma_bf16(sc[2 * nbp + 1], qfl[kk], kb_h[2], kb_h[3]);
            }
        }

        float tm0 = -1e30f, tm1 = -1e30f;
        #pragma unroll
        for (int nb = 0; nb < 4; ++nb) {
            int cb = k0 + nb * 8 + 2 * t;
            #pragma unroll
            for (int j = 0; j < 2; ++j) {
                int cc = cb + j;
                bool ok0 = (cc <= row0)     && (cc < n_init || row0 - cc < n_local);
                bool ok1 = (cc <= row0 + 8) && (cc < n_init || row0 + 8 - cc < n_local);
                sc[nb][j]     = ok0 ? sc[nb][j] * scale     : -1e30f;
                sc[nb][2 + j] = ok1 ? sc[nb][2 + j] * scale : -1e30f;
                tm0 = fmaxf(tm0, sc[nb][j]);
                tm1 = fmaxf(tm1, sc[nb][2 + j]);
            }
        }
        tm0 = fmaxf(tm0, __shfl_xor_sync(0xffffffffu, tm0, 1));
        tm0 = fmaxf(tm0, __shfl_xor_sync(0xffffffffu, tm0, 2));
        tm1 = fmaxf(tm1, __shfl_xor_sync(0xffffffffu, tm1, 1));
        tm1 = fmaxf(tm1, __shfl_xor_sync(0xffffffffu, tm1, 2));

        float mn0 = fmaxf(m_i[0], tm0), mn1 = fmaxf(m_i[1], tm1);
        float al0 = __expf(m_i[0] - mn0), al1 = __expf(m_i[1] - mn1);
        float rs0 = 0.f, rs1 = 0.f;
        #pragma unroll
        for (int nb = 0; nb < 4; ++nb) {
            #pragma unroll
            for (int j = 0; j < 2; ++j) {
                float p0 = __expf(sc[nb][j] - mn0);
                float p1 = __expf(sc[nb][2 + j] - mn1);
                sc[nb][j] = p0;  sc[nb][2 + j] = p1;
                rs0 += p0;  rs1 += p1;
            }
        }
        rs0 += __shfl_xor_sync(0xffffffffu, rs0, 1);
        rs0 += __shfl_xor_sync(0xffffffffu, rs0, 2);
        rs1 += __shfl_xor_sync(0xffffffffu, rs1, 1);
        rs1 += __shfl_xor_sync(0xffffffffu, rs1, 2);
        l_i[0] = l_i[0] * al0 + rs0;  m_i[0] = mn0;
        l_i[1] = l_i[1] * al1 + rs1;  m_i[1] = mn1;
        #pragma unroll
        for (int nb = 0; nb < 16; ++nb) {
            o[nb][0] *= al0;  o[nb][1] *= al0;
            o[nb][2] *= al1;  o[nb][3] *= al1;
        }

        uint32_t ph[4][2], pl[4][2];
        #pragma unroll
        for (int nb = 0; nb < 4; ++nb) {
            __nv_bfloat162 h0 = __floats2bfloat162_rn(sc[nb][0], sc[nb][1]);
            __nv_bfloat162 h1 = __floats2bfloat162_rn(sc[nb][2], sc[nb][3]);
            float r0 = sc[nb][0] - __low2float(h0), r1 = sc[nb][1] - __high2float(h0);
            float r2 = sc[nb][2] - __low2float(h1), r3 = sc[nb][3] - __high2float(h1);
            __nv_bfloat162 q0b = __floats2bfloat162_rn(r0, r1);
            __nv_bfloat162 q1b = __floats2bfloat162_rn(r2, r3);
            ph[nb][0] = *(uint32_t*)&h0;  ph[nb][1] = *(uint32_t*)&h1;
            pl[nb][0] = *(uint32_t*)&q0b; pl[nb][1] = *(uint32_t*)&q1b;
        }

        #pragma unroll
        for (int ks = 0; ks < 2; ++ks) {
            uint32_t aH[4] = { ph[2 * ks][0], ph[2 * ks][1],
                               ph[2 * ks + 1][0], ph[2 * ks + 1][1] };
            uint32_t aL[4] = { pl[2 * ks][0], pl[2 * ks][1],
                               pl[2 * ks + 1][0], pl[2 * ks + 1][1] };
            #pragma unroll
            for (int np = 0; np < 8; ++np) {
                uint32_t vh[4], vl[4];
                const int voff = (ks * 16 + (grp & 1) * 8 + (lane & 7)) * APAD
                               + (np * 2 + (grp >> 1)) * 8;
                ldsm_x4_t(vh, Vh + voff);
                ldsm_x4_t(vl, Vl + voff);
                mma_bf16(o[2 * np],     aH, vh[0], vh[1]);
                mma_bf16(o[2 * np],     aH, vl[0], vl[1]);
                mma_bf16(o[2 * np],     aL, vh[0], vh[1]);
                mma_bf16(o[2 * np + 1], aH, vh[2], vh[3]);
                mma_bf16(o[2 * np + 1], aH, vl[2], vl[3]);
                mma_bf16(o[2 * np + 1], aL, vh[2], vh[3]);
            }
        }

        t0 = t1;  t1 = t2;
        t2 = (t1 <= kb_max) ? nextv(t1 + 1, kb_max, q0, n_init, n_local) : kb_max + 1;
        ib = (ib + 1) % 3;
        if (t0 <= kb_max) {
            asm volatile("cp.async.wait_group 1;\n" ::);
            __syncthreads();
        }
    }

    // ---- fused epilogue: normalize + write fp16 packed-A fragments ----
    // fp16 A-frag layout == C-frag layout: no shuffles.
    {
        float inv0 = 1.f / l_i[0], inv1 = 1.f / l_i[1];
        #pragma unroll
        for (int nb = 0; nb < 16; ++nb) {
            o[nb][0] *= inv0;  o[nb][1] *= inv0;
            o[nb][2] *= inv1;  o[nb][3] *= inv1;
        }
        const size_t rb = (size_t)(blockIdx.x >> 1);
        const size_t mb = (size_t)((blockIdx.x & 1) * 4 + warp);
        const size_t base = (rb << 16) | (mb << 5) | (size_t)lane;
        #pragma unroll
        for (int m = 0; m < 8; ++m) {
            float4 pv;
            pv.x = __uint_as_float(pkh(o[2 * m][0],     o[2 * m][1]));
            pv.y = __uint_as_float(pkh(o[2 * m][2],     o[2 * m][3]));
            pv.z = __uint_as_float(pkh(o[2 * m + 1][0], o[2 * m + 1][1]));
            pv.w = __uint_as_float(pkh(o[2 * m + 1][2], o[2 * m + 1][3]));
            const size_t ksg = (size_t)(h * 8 + m);
            PAout[base + (ksg << 8)] = pv;
        }
    }
}

// ---------------------------------------------------------------------------
extern "C" void kernel_launch(void* const* d_in, const int* in_sizes, int n_in,
                              void* d_out, int out_size) {
    const float* hs = (const float*)d_in[0];
    const float* Wq = (const float*)d_in[1];
    const float* Wk = (const float*)d_in[2];
    const float* Wv = (const float*)d_in[3];
    const float* Wo = (const float*)d_in[4];
    const int* n_init  = (const int*)d_in[5];
    const int* n_local = (const int*)d_in[6];
    float* out = (float*)d_out;

    __nv_bfloat16 *qh, *ql, *kh, *kl, *vh, *vl;
    cudaGetSymbolAddress((void**)&qh, g_qh);  cudaGetSymbolAddress((void**)&ql, g_ql);
    cudaGetSymbolAddress((void**)&kh, g_kh);  cudaGetSymbolAddress((void**)&kl, g_kl);
    cudaGetSymbolAddress((void**)&vh, g_vh);  cudaGetSymbolAddress((void**)&vl, g_vl);
    float4 *pa_hs, *pa_at, *pb_wq, *pb_wk, *pb_wv, *pb_wo;
    cudaGetSymbolAddress((void**)&pa_hs, g_pa_hs);
    cudaGetSymbolAddress((void**)&pa_at, g_pa_at);
    cudaGetSymbolAddress((void**)&pb_wq, g_pb_wq);
    cudaGetSymbolAddress((void**)&pb_wk, g_pb_wk);
    cudaGetSymbolAddress((void**)&pb_wv, g_pb_wv);
    cudaGetSymbolAddress((void**)&pb_wo, g_pb_wo);

    static int attr_set = 0;
    if (!attr_set) {
        cudaFuncSetAttribute(attn_cp,  cudaFuncAttributeMaxDynamicSharedMemorySize, ASMEM2);
        cudaFuncSetAttribute(gemm_pk2, cudaFuncAttributeMaxDynamicSharedMemorySize, PK2_SMEM);
        attr_set = 1;
    }

    pack_all<<<PACK_BLOCKS, 256>>>(hs, Wq, Wk, Wv, Wo,
                                   pa_hs, pb_wq, pb_wk, pb_wv, pb_wo);

    gemm_pk2<<<dim3(24, S_LEN / 128), 256, PK2_SMEM>>>(
        pa_hs,
        pb_wq, 16, nullptr, qh, ql, HID,
        pb_wk, 4,  nullptr, kh, kl, KVDIM,
        pb_wv, 4,  nullptr, vh, vl, KVDIM,
        1);

    attn_cp<<<dim3(S_LEN / ABQ, NH), 128, ASMEM2>>>(qh, ql, kh, kl, vh, vl,
                                                    pa_at, n_init, n_local);

    gemm_pk2<<<dim3(16, S_LEN / 128), 256, PK2_SMEM>>>(
        pa_at,
        pb_wo, 16, out, nullptr, nullptr, HID,
        pb_wo, 0,  out, nullptr, nullptr, HID,
        pb_wo, 0,  out, nullptr, nullptr, HID,
        0);
}

// round 16
// speedup vs baseline: 1.6352x; 1.0525x over previous
#include <cuda_runtime.h>
#include <cuda_bf16.h>
#include <cuda_fp16.h>
#include <math.h>
#include <stdint.h>

#define S_LEN 2048
#define HID   4096
#define NH    32
#define NKV   8
#define HD    128
#define KVDIM 1024
#define KDIM  4096
#define K16S  (KDIM / 16)    // 256 k16 units
#define NS128 (KDIM / 128)   // 32 k128 stages

// ---------------- scratch ----------------
__device__ __align__(16) __nv_bfloat16 g_qh[S_LEN * HID],  g_ql[S_LEN * HID];
__device__ __align__(16) __nv_bfloat16 g_kh[S_LEN * KVDIM], g_kl[S_LEN * KVDIM];
__device__ __align__(16) __nv_bfloat16 g_v1[S_LEN * KVDIM];   // fp16 bits
__device__ float4 g_pa_hs[(S_LEN / 128) * K16S * 256];
__device__ float4 g_pa_at[(S_LEN / 128) * K16S * 256];
__device__ float4 g_pb_wq[(HID / 128) * K16S * 256];
__device__ float4 g_pb_wk[(KVDIM / 128) * K16S * 256];
__device__ float4 g_pb_wv[(KVDIM / 128) * K16S * 256];
__device__ float4 g_pb_wo[(HID / 128) * K16S * 256];

// ---------------- helpers ----------------
__device__ __forceinline__ uint32_t smem_u32(const void* p) {
    uint32_t a;
    asm("{ .reg .u64 t; cvta.to.shared.u64 t, %1; cvt.u32.u64 %0, t; }" : "=r"(a) : "l"(p));
    return a;
}
__device__ __forceinline__ void cp_async16s(uint32_t s, const void* g) {
    asm volatile("cp.async.cg.shared.global [%0], [%1], 16;\n" :: "r"(s), "l"(g));
}
__device__ __forceinline__ uint32_t pkh(float a, float b) {
    __half2 h = __floats2half2_rn(a, b);
    return *(uint32_t*)&h;
}
__device__ __forceinline__ void mma_fp16(float c[4], const uint32_t a[4],
                                         uint32_t b0, uint32_t b1) {
    asm volatile(
        "mma.sync.aligned.m16n8k16.row.col.f32.f16.f16.f32 "
        "{%0,%1,%2,%3},{%4,%5,%6,%7},{%8,%9},{%0,%1,%2,%3};"
        : "+f"(c[0]), "+f"(c[1]), "+f"(c[2]), "+f"(c[3])
        : "r"(a[0]), "r"(a[1]), "r"(a[2]), "r"(a[3]), "r"(b0), "r"(b1));
}
__device__ __forceinline__ void mma_bf16(float c[4], const uint32_t a[4],
                                         uint32_t b0, uint32_t b1) {
    asm volatile(
        "mma.sync.aligned.m16n8k16.row.col.f32.bf16.bf16.f32 "
        "{%0,%1,%2,%3},{%4,%5,%6,%7},{%8,%9},{%0,%1,%2,%3};"
        : "+f"(c[0]), "+f"(c[1]), "+f"(c[2]), "+f"(c[3])
        : "r"(a[0]), "r"(a[1]), "r"(a[2]), "r"(a[3]), "r"(b0), "r"(b1));
}
__device__ __forceinline__ void ldsm_x4(uint32_t r[4], const void* p) {
    uint32_t a = smem_u32(p);
    asm volatile("ldmatrix.sync.aligned.m8n8.x4.shared.b16 {%0,%1,%2,%3}, [%4];"
                 : "=r"(r[0]), "=r"(r[1]), "=r"(r[2]), "=r"(r[3]) : "r"(a));
}
__device__ __forceinline__ void ldsm_x4_t(uint32_t r[4], const void* p) {
    uint32_t a = smem_u32(p);
    asm volatile("ldmatrix.sync.aligned.m8n8.x4.trans.shared.b16 {%0,%1,%2,%3}, [%4];"
                 : "=r"(r[0]), "=r"(r[1]), "=r"(r[2]), "=r"(r[3]) : "r"(a));
}

// ---------------------------------------------------------------------------
// Unified pack: fp16 fragment-pack for all 5 tensors (round-15 kernel).
// ---------------------------------------------------------------------------
#define SEG_HS 16
#define SEG_WQ 48
#define SEG_WK 56
#define SEG_WV 64
#define SEG_WO 96
#define PACK_BLOCKS (SEG_WO * 256)

__global__ __launch_bounds__(256) void pack_all(
    const float* __restrict__ hs, const float* __restrict__ Wq,
    const float* __restrict__ Wk, const float* __restrict__ Wv,
    const float* __restrict__ Wo,
    float4* __restrict__ Phs, float4* __restrict__ Pwq,
    float4* __restrict__ Pwk, float4* __restrict__ Pwv,
    float4* __restrict__ Pwo) {
    __shared__ float S[128 * 36];
    const int tid  = threadIdx.x;
    const int tile = blockIdx.x;
    const int ks   = tile & 255;
    const int seg  = tile >> 8;

    const float* X;  float4* P;  int rb, amode;
    if (seg < SEG_HS)      { X = hs; P = Phs; rb = seg;          amode = 1; }
    else if (seg < SEG_WQ) { X = Wq; P = Pwq; rb = seg - SEG_HS; amode = 0; }
    else if (seg < SEG_WK) { X = Wk; P = Pwk; rb = seg - SEG_WQ; amode = 0; }
    else if (seg < SEG_WV) { X = Wv; P = Pwv; rb = seg - SEG_WK; amode = 0; }
    else                   { X = Wo; P = Pwo; rb = seg - SEG_WV; amode = 0; }

    const float* Xb = X + (size_t)rb * 128 * KDIM + ks * 16;
    #pragma unroll
    for (int j = 0; j < 2; ++j) {
        int li = tid + j * 256;
        int row = li >> 2, c4 = (li & 3) << 2;
        float4 v = *(const float4*)(Xb + (size_t)row * KDIM + c4);
        *(float4*)&S[row * 36 + c4] = v;
    }
    __syncthreads();

    const int lane = tid & 31, blk = tid >> 5;
    const int g = lane >> 2, t = lane & 3;
    float4 pv;
    if (amode) {
        int r = blk * 16 + g;
        pv.x = __uint_as_float(pkh(S[r * 36 + 2 * t],       S[r * 36 + 2 * t + 1]));
        pv.y = __uint_as_float(pkh(S[(r + 8) * 36 + 2 * t], S[(r + 8) * 36 + 2 * t + 1]));
        pv.z = __uint_as_float(pkh(S[r * 36 + 2 * t + 8],   S[r * 36 + 2 * t + 9]));
        pv.w = __uint_as_float(pkh(S[(r + 8) * 36 + 2 * t + 8], S[(r + 8) * 36 + 2 * t + 9]));
    } else {
        int c0 = blk * 16 + g, c1 = c0 + 8;
        pv.x = __uint_as_float(pkh(S[c0 * 36 + 2 * t],     S[c0 * 36 + 2 * t + 1]));
        pv.y = __uint_as_float(pkh(S[c0 * 36 + 2 * t + 8], S[c0 * 36 + 2 * t + 9]));
        pv.z = __uint_as_float(pkh(S[c1 * 36 + 2 * t],     S[c1 * 36 + 2 * t + 1]));
        pv.w = __uint_as_float(pkh(S[c1 * 36 + 2 * t + 8], S[c1 * 36 + 2 * t + 9]));
    }
    P[(((size_t)rb << 8 | ks) << 8) + tid] = pv;
}

// ---------------------------------------------------------------------------
// Fragment-packed FP16 GEMM: CTA 128x256, warp 64x64, k=128/stage, 2-stage.
// Per-segment output mode: 0=f32, 1=split bf16 (hi+lo), 2=fp16 single.
// ---------------------------------------------------------------------------
#define STG_F4  6144
#define STG_BY  (STG_F4 * 16)
#define PK2_SMEM (2 * STG_BY)

__global__ __launch_bounds__(256, 1)
void gemm_pk2(const float4* __restrict__ PA,
              const float4* __restrict__ B0, int nt0, float* C0f,
              __nv_bfloat16* C0h, __nv_bfloat16* C0l, int ld0, int m0,
              const float4* __restrict__ B1, int nt1, float* C1f,
              __nv_bfloat16* C1h, __nv_bfloat16* C1l, int ld1, int m1,
              const float4* __restrict__ B2, int nt2, float* C2f,
              __nv_bfloat16* C2h, __nv_bfloat16* C2l, int ld2, int m2) {
    extern __shared__ float4 sm4[];
    const int tid = threadIdx.x, warp = tid >> 5, lane = tid & 31;
    const int g = lane >> 2, t = lane & 3;
    const int wm = warp & 1;
    const int wn = warp >> 1;
    const uint32_t sb = smem_u32(sm4);

    int nt = blockIdx.x;
    const float4* PB;  float* Cf;  __nv_bfloat16 *Ch, *Cl;  int ld, mode;
    if (nt < nt0)            { PB = B0; Cf = C0f; Ch = C0h; Cl = C0l; ld = ld0; mode = m0; }
    else if (nt < nt0 + nt1) { nt -= nt0;       PB = B1; Cf = C1f; Ch = C1h; Cl = C1l; ld = ld1; mode = m1; }
    else                     { nt -= nt0 + nt1; PB = B2; Cf = C2f; Ch = C2h; Cl = C2l; ld = ld2; mode = m2; }

    const size_t abase  = (size_t)blockIdx.y << 16;
    const size_t bbase0 = (size_t)(2 * nt)     << 16;
    const size_t bbase1 = (size_t)(2 * nt + 1) << 16;

    float c[4][8][4];
    #pragma unroll
    for (int mt = 0; mt < 4; mt++)
        #pragma unroll
        for (int ntb = 0; ntb < 8; ntb++)
            #pragma unroll
            for (int i = 0; i < 4; i++) c[mt][ntb][i] = 0.f;

    #define STAGE3(s_)                                                          \
        do {                                                                    \
            const uint32_t db = sb + (uint32_t)((s_) & 1) * STG_BY;             \
            const size_t koff = (size_t)(s_) * 2048;                            \
            _Pragma("unroll")                                                   \
            for (int i_ = 0; i_ < 24; ++i_) {                                   \
                int cix = tid + i_ * 256;                                       \
                const float4* src;                                              \
                if (cix < 2048)       src = PA + abase  + koff + cix;           \
                else if (cix < 4096)  src = PB + bbase0 + koff + (cix - 2048);  \
                else                  src = PB + bbase1 + koff + (cix - 4096);  \
                cp_async16s(db + (uint32_t)cix * 16u, src);                     \
            }                                                                   \
            asm volatile("cp.async.commit_group;\n" ::);                        \
        } while (0)

    STAGE3(0);
    STAGE3(1);

    const int bblk = wn >> 1;
    const int bnp0 = (wn & 1) * 4;

    for (int s = 0; s < NS128; ++s) {
        if (s + 1 < NS128) asm volatile("cp.async.wait_group 1;\n" ::);
        else               asm volatile("cp.async.wait_group 0;\n" ::);
        __syncthreads();

        const float4* As4 = sm4 + (s & 1) * STG_F4;
        const float4* Bs4 = As4 + 2048 + bblk * 2048;
        #pragma unroll
        for (int kk = 0; kk < 8; ++kk) {
            float4 av[4], bv[4];
            #pragma unroll
            for (int mt = 0; mt < 4; ++mt)
                av[mt] = As4[kk * 256 + (wm * 4 + mt) * 32 + lane];
            #pragma unroll
            for (int p = 0; p < 4; ++p)
                bv[p] = Bs4[kk * 256 + (bnp0 + p) * 32 + lane];
            #pragma unroll
            for (int mt = 0; mt < 4; ++mt) {
                uint32_t a[4] = { __float_as_uint(av[mt].x), __float_as_uint(av[mt].y),
                                  __float_as_uint(av[mt].z), __float_as_uint(av[mt].w) };
                #pragma unroll
                for (int p = 0; p < 4; ++p) {
                    mma_fp16(c[mt][2 * p],     a, __float_as_uint(bv[p].x), __float_as_uint(bv[p].y));
                    mma_fp16(c[mt][2 * p + 1], a, __float_as_uint(bv[p].z), __float_as_uint(bv[p].w));
                }
            }
        }

        if (s + 2 < NS128) {
            __syncthreads();
            STAGE3(s + 2);
        }
    }

    const int bm = blockIdx.y * 128, bn = nt * 256;
    #pragma unroll
    for (int mt = 0; mt < 4; ++mt) {
        #pragma unroll
        for (int ntb = 0; ntb < 8; ++ntb) {
            const int row = bm + wm * 64 + mt * 16 + g;
            const int col = bn + wn * 64 + ntb * 8 + 2 * t;
            size_t e0 = (size_t)row * ld + col;
            size_t e1 = (size_t)(row + 8) * ld + col;
            if (mode == 0) {
                *(float2*)&Cf[e0] = make_float2(c[mt][ntb][0], c[mt][ntb][1]);
                *(float2*)&Cf[e1] = make_float2(c[mt][ntb][2], c[mt][ntb][3]);
            } else if (mode == 1) {
                __nv_bfloat162 h0 = __floats2bfloat162_rn(c[mt][ntb][0], c[mt][ntb][1]);
                __nv_bfloat162 h1 = __floats2bfloat162_rn(c[mt][ntb][2], c[mt][ntb][3]);
                __nv_bfloat162 l0 = __floats2bfloat162_rn(c[mt][ntb][0] - __low2float(h0),
                                                          c[mt][ntb][1] - __high2float(h0));
                __nv_bfloat162 l1 = __floats2bfloat162_rn(c[mt][ntb][2] - __low2float(h1),
                                                          c[mt][ntb][3] - __high2float(h1));
                *(__nv_bfloat162*)&Ch[e0] = h0;  *(__nv_bfloat162*)&Cl[e0] = l0;
                *(__nv_bfloat162*)&Ch[e1] = h1;  *(__nv_bfloat162*)&Cl[e1] = l1;
            } else {
                *(uint32_t*)&Ch[e0] = pkh(c[mt][ntb][0], c[mt][ntb][1]);
                *(uint32_t*)&Ch[e1] = pkh(c[mt][ntb][2], c[mt][ntb][3]);
            }
        }
    }
}

// ---------------------------------------------------------------------------
// Attention v5: ABQ=64, ABK=32, 4 warps, 2 CTAs/SM, Q hoisted, 3-buffer ring.
// QK: bf16 3-term (unchanged). PV: P split fp16 (hi/lo) x V single fp16
// -> 2 MMAs per output pair, V staging/ldsm halved.
// ---------------------------------------------------------------------------
#define ABQ  64
#define ABK  32
#define APAD 136
#define QELEMS (2 * ABQ * APAD)        // 17408 bf16
#define KVBUF3 (3 * ABK * APAD)        // 13056 bf16
#define ASMEM2 ((QELEMS + 2 * KVBUF3) * 2)   // 87040 bytes

__device__ __forceinline__ int nextv(int kb, int kb_max, int q0, int n_init, int n_local) {
    while (kb <= kb_max) {
        int k0 = kb * ABK;
        if (!(k0 >= n_init && (q0 - (k0 + ABK - 1)) >= n_local)) break;
        kb++;
    }
    return kb;
}

__global__ __launch_bounds__(128, 2) void attn_cp(
    const __nv_bfloat16* __restrict__ Qhg, const __nv_bfloat16* __restrict__ Qlg,
    const __nv_bfloat16* __restrict__ Khg, const __nv_bfloat16* __restrict__ Klg,
    const __nv_bfloat16* __restrict__ Vg,   // fp16 bits
    float4* __restrict__ PAout,
    const int* __restrict__ n_init_p, const int* __restrict__ n_local_p) {

    extern __shared__ __nv_bfloat16 smb[];
    __nv_bfloat16* Qh = smb;
    __nv_bfloat16* Ql = smb + ABQ * APAD;
    // buffer bases (elems): buf0 reuses Q region after hoist
    const uint32_t boffs[3] = {0u, QELEMS, QELEMS + KVBUF3};

    const int h   = blockIdx.y;
    const int q0  = blockIdx.x * ABQ;
    const int hkv = h >> 2;
    const int n_init  = *n_init_p;
    const int n_local = *n_local_p;

    const int tid  = threadIdx.x;
    const int warp = tid >> 5;
    const int lane = tid & 31;
    const int g    = lane >> 2;
    const int t    = lane & 3;
    const int grp  = lane >> 3;

    const int kb_max = (q0 + ABQ - 1) / ABK;

    // KV tile: 3 sub-tensors (Kh, Kl, V) x 32 rows x 16 chunks = 1536 cp.async
    #define STAGE_KV(bufp, k0_)                                                  \
        do {                                                                     \
            const __nv_bfloat16* gsrc_[3] = { Khg, Klg, Vg };                    \
            _Pragma("unroll")                                                    \
            for (int it_ = 0; it_ < 12; ++it_) {                                 \
                int idx = tid + it_ * 128;                                       \
                int ts_ = idx >> 9, rc_ = idx & 511;                             \
                int row_ = rc_ >> 4, ch_ = rc_ & 15;                             \
                const __nv_bfloat16* src = gsrc_[ts_] +                          \
                    (size_t)((k0_) + row_) * KVDIM + hkv * HD + ch_ * 8;         \
                __nv_bfloat16* dst = (bufp) + ts_ * (ABK * APAD)                 \
                    + row_ * APAD + ch_ * 8;                                     \
                cp_async16s(smem_u32(dst), src);                                 \
            }                                                                    \
        } while (0)

    int t0 = nextv(0, kb_max, q0, n_init, n_local);
    int t1 = (t0 <= kb_max) ? nextv(t0 + 1, kb_max, q0, n_init, n_local) : kb_max + 1;
    int t2 = (t1 <= kb_max) ? nextv(t1 + 1, kb_max, q0, n_init, n_local) : kb_max + 1;

    {
        #pragma unroll
        for (int it = 0; it < 16; ++it) {
            int idx = tid + it * 128;
            int ts = idx >> 10, rc = idx & 1023;
            int row = rc >> 4, ch = rc & 15;
            const __nv_bfloat16* src = (ts ? Qlg : Qhg) +
                (size_t)(q0 + row) * HID + h * HD + ch * 8;
            __nv_bfloat16* dst = (ts ? Ql : Qh) + row * APAD + ch * 8;
            cp_async16s(smem_u32(dst), src);
        }
    }
    if (t0 <= kb_max) STAGE_KV(smb + boffs[1], t0 * ABK);
    asm volatile("cp.async.commit_group;\n" ::);
    if (t1 <= kb_max) STAGE_KV(smb + boffs[2], t1 * ABK);
    asm volatile("cp.async.commit_group;\n" ::);

    uint32_t qfh[8][4], qfl[8][4];
    asm volatile("cp.async.wait_group 1;\n" ::);
    __syncthreads();
    #pragma unroll
    for (int kk = 0; kk < 8; ++kk) {
        const int aoff = (warp * 16 + (lane & 15)) * APAD + kk * 16 + (lane >> 4) * 8;
        ldsm_x4(qfh[kk], Qh + aoff);
        ldsm_x4(qfl[kk], Ql + aoff);
    }
    __syncthreads();   // Q reads done before buf0 is reused

    float o[16][4];
    float m_i[2] = {-1e30f, -1e30f};
    float l_i[2] = {0.f, 0.f};
    #pragma unroll
    for (int nb = 0; nb < 16; nb++)
        #pragma unroll
        for (int j = 0; j < 4; j++) o[nb][j] = 0.f;

    const int   row0  = q0 + warp * 16 + g;
    const float scale = 0.08838834764831845f;
    int ib = 1;

    while (t0 <= kb_max) {
        const int k0 = t0 * ABK;

        if (t2 <= kb_max) STAGE_KV(smb + boffs[(ib + 2) % 3], t2 * ABK);
        asm volatile("cp.async.commit_group;\n" ::);

        __nv_bfloat16* Kh = smb + boffs[ib];
        __nv_bfloat16* Kl = Kh + ABK * APAD;
        __nv_bfloat16* Vv = Kl + ABK * APAD;

        // ---- S = Q @ K^T (bf16 3-term, Q from registers) ----
        float sc[4][4];
        #pragma unroll
        for (int nb = 0; nb < 4; nb++)
            #pragma unroll
            for (int j = 0; j < 4; j++) sc[nb][j] = 0.f;

        #pragma unroll
        for (int kk = 0; kk < 8; ++kk) {
            #pragma unroll
            for (int nbp = 0; nbp < 2; ++nbp) {
                uint32_t kb_h[4], kb_l[4];
                const int boff = (nbp * 16 + (grp >> 1) * 8 + (lane & 7)) * APAD
                               + kk * 16 + (grp & 1) * 8;
                ldsm_x4(kb_h, Kh + boff);
                ldsm_x4(kb_l, Kl + boff);
                mma_bf16(sc[2 * nbp],     qfh[kk], kb_h[0], kb_h[1]);
                mma_bf16(sc[2 * nbp],     qfh[kk], kb_l[0], kb_l[1]);
                mma_bf16(sc[2 * nbp],     qfl[kk], kb_h[0], kb_h[1]);
                mma_bf16(sc[2 * nbp + 1], qfh[kk], kb_h[2], kb_h[3]);
                mma_bf16(sc[2 * nbp + 1], qfh[kk], kb_l[2], kb_l[3]);
                mma_bf16(sc[2 * nbp + 1], qfl[kk], kb_h[2], kb_h[3]);
            }
        }

        // ---- mask + online softmax ----
        float tm0 = -1e30f, tm1 = -1e30f;
        #pragma unroll
        for (int nb = 0; nb < 4; ++nb) {
            int cb = k0 + nb * 8 + 2 * t;
            #pragma unroll
            for (int j = 0; j < 2; ++j) {
                int cc = cb + j;
                bool ok0 = (cc <= row0)     && (cc < n_init || row0 - cc < n_local);
                bool ok1 = (cc <= row0 + 8) && (cc < n_init || row0 + 8 - cc < n_local);
                sc[nb][j]     = ok0 ? sc[nb][j] * scale     : -1e30f;
                sc[nb][2 + j] = ok1 ? sc[nb][2 + j] * scale : -1e30f;
                tm0 = fmaxf(tm0, sc[nb][j]);
                tm1 = fmaxf(tm1, sc[nb][2 + j]);
            }
        }
        tm0 = fmaxf(tm0, __shfl_xor_sync(0xffffffffu, tm0, 1));
        tm0 = fmaxf(tm0, __shfl_xor_sync(0xffffffffu, tm0, 2));
        tm1 = fmaxf(tm1, __shfl_xor_sync(0xffffffffu, tm1, 1));
        tm1 = fmaxf(tm1, __shfl_xor_sync(0xffffffffu, tm1, 2));

        float mn0 = fmaxf(m_i[0], tm0), mn1 = fmaxf(m_i[1], tm1);
        float al0 = __expf(m_i[0] - mn0), al1 = __expf(m_i[1] - mn1);
        float rs0 = 0.f, rs1 = 0.f;
        #pragma unroll
        for (int nb = 0; nb < 4; ++nb) {
            #pragma unroll
            for (int j = 0; j < 2; ++j) {
                float p0 = __expf(sc[nb][j] - mn0);
                float p1 = __expf(sc[nb][2 + j] - mn1);
                sc[nb][j] = p0;  sc[nb][2 + j] = p1;
                rs0 += p0;  rs1 += p1;
            }
        }
        rs0 += __shfl_xor_sync(0xffffffffu, rs0, 1);
        rs0 += __shfl_xor_sync(0xffffffffu, rs0, 2);
        rs1 += __shfl_xor_sync(0xffffffffu, rs1, 1);
        rs1 += __shfl_xor_sync(0xffffffffu, rs1, 2);
        l_i[0] = l_i[0] * al0 + rs0;  m_i[0] = mn0;
        l_i[1] = l_i[1] * al1 + rs1;  m_i[1] = mn1;
        #pragma unroll
        for (int nb = 0; nb < 16; ++nb) {
            o[nb][0] *= al0;  o[nb][1] *= al0;
            o[nb][2] *= al1;  o[nb][3] *= al1;
        }

        // ---- pack P fragments as fp16 hi/lo from registers ----
        uint32_t ph[4][2], pl[4][2];
        #pragma unroll
        for (int nb = 0; nb < 4; ++nb) {
            uint32_t u0 = pkh(sc[nb][0], sc[nb][1]);
            uint32_t u1 = pkh(sc[nb][2], sc[nb][3]);
            __half2 h0 = *(__half2*)&u0;
            __half2 h1 = *(__half2*)&u1;
            float r0 = sc[nb][0] - __half2float(__low2half(h0));
            float r1 = sc[nb][1] - __half2float(__high2half(h0));
            float r2 = sc[nb][2] - __half2float(__low2half(h1));
            float r3 = sc[nb][3] - __half2float(__high2half(h1));
            ph[nb][0] = u0;  ph[nb][1] = u1;
            pl[nb][0] = pkh(r0, r1);
            pl[nb][1] = pkh(r2, r3);
        }

        // ---- O += P @ V  (P split fp16 x V single fp16: 2 MMAs/pair) ----
        #pragma unroll
        for (int ks = 0; ks < 2; ++ks) {
            uint32_t aH[4] = { ph[2 * ks][0], ph[2 * ks][1],
                               ph[2 * ks + 1][0], ph[2 * ks + 1][1] };
            uint32_t aL[4] = { pl[2 * ks][0], pl[2 * ks][1],
                               pl[2 * ks + 1][0], pl[2 * ks + 1][1] };
            #pragma unroll
            for (int np = 0; np < 8; ++np) {
                uint32_t vh[4];
                const int voff = (ks * 16 + (grp & 1) * 8 + (lane & 7)) * APAD
                               + (np * 2 + (grp >> 1)) * 8;
                ldsm_x4_t(vh, Vv + voff);
                mma_fp16(o[2 * np],     aH, vh[0], vh[1]);
                mma_fp16(o[2 * np],     aL, vh[0], vh[1]);
                mma_fp16(o[2 * np + 1], aH, vh[2], vh[3]);
                mma_fp16(o[2 * np + 1], aL, vh[2], vh[3]);
            }
        }

        t0 = t1;  t1 = t2;
        t2 = (t1 <= kb_max) ? nextv(t1 + 1, kb_max, q0, n_init, n_local) : kb_max + 1;
        ib = (ib + 1) % 3;
        if (t0 <= kb_max) {
            asm volatile("cp.async.wait_group 1;\n" ::);
            __syncthreads();
        }
    }

    // ---- fused epilogue: normalize + write fp16 packed-A fragments ----
    {
        float inv0 = 1.f / l_i[0], inv1 = 1.f / l_i[1];
        #pragma unroll
        for (int nb = 0; nb < 16; ++nb) {
            o[nb][0] *= inv0;  o[nb][1] *= inv0;
            o[nb][2] *= inv1;  o[nb][3] *= inv1;
        }
        const size_t rb = (size_t)(blockIdx.x >> 1);
        const size_t mb = (size_t)((blockIdx.x & 1) * 4 + warp);
        const size_t base = (rb << 16) | (mb << 5) | (size_t)lane;
        #pragma unroll
        for (int m = 0; m < 8; ++m) {
            float4 pv;
            pv.x = __uint_as_float(pkh(o[2 * m][0],     o[2 * m][1]));
            pv.y = __uint_as_float(pkh(o[2 * m][2],     o[2 * m][3]));
            pv.z = __uint_as_float(pkh(o[2 * m + 1][0], o[2 * m + 1][1]));
            pv.w = __uint_as_float(pkh(o[2 * m + 1][2], o[2 * m + 1][3]));
            const size_t ksg = (size_t)(h * 8 + m);
            PAout[base + (ksg << 8)] = pv;
        }
    }
}

// ---------------------------------------------------------------------------
extern "C" void kernel_launch(void* const* d_in, const int* in_sizes, int n_in,
                              void* d_out, int out_size) {
    const float* hs = (const float*)d_in[0];
    const float* Wq = (const float*)d_in[1];
    const float* Wk = (const float*)d_in[2];
    const float* Wv = (const float*)d_in[3];
    const float* Wo = (const float*)d_in[4];
    const int* n_init  = (const int*)d_in[5];
    const int* n_local = (const int*)d_in[6];
    float* out = (float*)d_out;

    __nv_bfloat16 *qh, *ql, *kh, *kl, *v1;
    cudaGetSymbolAddress((void**)&qh, g_qh);  cudaGetSymbolAddress((void**)&ql, g_ql);
    cudaGetSymbolAddress((void**)&kh, g_kh);  cudaGetSymbolAddress((void**)&kl, g_kl);
    cudaGetSymbolAddress((void**)&v1, g_v1);
    float4 *pa_hs, *pa_at, *pb_wq, *pb_wk, *pb_wv, *pb_wo;
    cudaGetSymbolAddress((void**)&pa_hs, g_pa_hs);
    cudaGetSymbolAddress((void**)&pa_at, g_pa_at);
    cudaGetSymbolAddress((void**)&pb_wq, g_pb_wq);
    cudaGetSymbolAddress((void**)&pb_wk, g_pb_wk);
    cudaGetSymbolAddress((void**)&pb_wv, g_pb_wv);
    cudaGetSymbolAddress((void**)&pb_wo, g_pb_wo);

    static int attr_set = 0;
    if (!attr_set) {
        cudaFuncSetAttribute(attn_cp,  cudaFuncAttributeMaxDynamicSharedMemorySize, ASMEM2);
        cudaFuncSetAttribute(gemm_pk2, cudaFuncAttributeMaxDynamicSharedMemorySize, PK2_SMEM);
        attr_set = 1;
    }

    pack_all<<<PACK_BLOCKS, 256>>>(hs, Wq, Wk, Wv, Wo,
                                   pa_hs, pb_wq, pb_wk, pb_wv, pb_wo);

    // Fused QKV: q,k split bf16 (mode 1); v single fp16 (mode 2)
    gemm_pk2<<<dim3(24, S_LEN / 128), 256, PK2_SMEM>>>(
        pa_hs,
        pb_wq, 16, nullptr, qh, ql, HID,   1,
        pb_wk, 4,  nullptr, kh, kl, KVDIM, 1,
        pb_wv, 4,  nullptr, v1, nullptr, KVDIM, 2);

    attn_cp<<<dim3(S_LEN / ABQ, NH), 128, ASMEM2>>>(qh, ql, kh, kl, v1,
                                                    pa_at, n_init, n_local);

    // Output projection (f32 out)
    gemm_pk2<<<dim3(16, S_LEN / 128), 256, PK2_SMEM>>>(
        pa_at,
        pb_wo, 16, out, nullptr, nullptr, HID, 0,
        pb_wo, 0,  out, nullptr, nullptr, HID, 0,
        pb_wo, 0,  out, nullptr, nullptr, HID, 0);
}